// round 1
// baseline (speedup 1.0000x reference)
#include <cuda_runtime.h>

// Problem dims
#define Bb 2
#define Ss 2048
#define Ee 1024
#define Hh 16
#define Dd 64
// M = Bb*Ss = 4096 rows

// Scratch: [B,H,S,D] fp32, 16.8MB each
__device__ float g_Q[(size_t)Bb * Hh * Ss * Dd];
__device__ float g_K[(size_t)Bb * Hh * Ss * Dd];
__device__ float g_V[(size_t)Bb * Hh * Ss * Dd];
__device__ float g_O[(size_t)Bb * Hh * Ss * Dd];

// ---------------------------------------------------------------------------
// Kernel 1: QKV projections.  C[4096,1024] = x[4096,1024] @ W[1024,1024],
// written into [B,H,S,D] layout.  blockIdx.z selects Wq/Wk/Wv.
// 64x64 tile, BK=16, 16x16 threads, 4x4 per-thread micro-tile.
// ---------------------------------------------------------------------------
__global__ __launch_bounds__(256) void qkv_kernel(
    const float* __restrict__ x,
    const float* __restrict__ Wq,
    const float* __restrict__ Wk,
    const float* __restrict__ Wv)
{
    __shared__ float As[16][68];  // [k][m], padded for 16B-aligned float4 reads
    __shared__ float Bs[16][64];  // [k][n]

    const int tx = threadIdx.x, ty = threadIdx.y;
    const int tid = ty * 16 + tx;
    const int n0 = blockIdx.x * 64;
    const int m0 = blockIdx.y * 64;

    const float* W = (blockIdx.z == 0) ? Wq : (blockIdx.z == 1) ? Wk : Wv;
    float* Out = (blockIdx.z == 0) ? g_Q : (blockIdx.z == 1) ? g_K : g_V;

    const int arow = tid >> 2;          // 0..63
    const int acol = (tid & 3) * 4;     // 0,4,8,12
    const int brow = tid >> 4;          // 0..15
    const int bcol = (tid & 15) * 4;    // 0..60

    const float* Ap = x + (size_t)(m0 + arow) * Ee + acol;
    const float* Bp = W + (size_t)brow * Ee + n0 + bcol;

    float acc[4][4] = {};

    for (int k0 = 0; k0 < Ee; k0 += 16) {
        float4 a = *(const float4*)(Ap + k0);
        float4 b = *(const float4*)(Bp + (size_t)k0 * Ee);
        As[acol + 0][arow] = a.x;
        As[acol + 1][arow] = a.y;
        As[acol + 2][arow] = a.z;
        As[acol + 3][arow] = a.w;
        *(float4*)&Bs[brow][bcol] = b;
        __syncthreads();
#pragma unroll
        for (int kk = 0; kk < 16; kk++) {
            float4 av = *(const float4*)&As[kk][ty * 4];
            float4 bv = *(const float4*)&Bs[kk][tx * 4];
            float ar[4] = {av.x, av.y, av.z, av.w};
            float br[4] = {bv.x, bv.y, bv.z, bv.w};
#pragma unroll
            for (int i = 0; i < 4; i++)
#pragma unroll
                for (int j = 0; j < 4; j++)
                    acc[i][j] += ar[i] * br[j];
        }
        __syncthreads();
    }

    // Epilogue: scatter into [B,H,S,D]
#pragma unroll
    for (int i = 0; i < 4; i++) {
        int row = m0 + ty * 4 + i;
        int bb = row >> 11;             // row / S
        int s = row & (Ss - 1);
        int col = n0 + tx * 4;
        int h = col >> 6;
        int d = col & 63;
        float4 v = make_float4(acc[i][0], acc[i][1], acc[i][2], acc[i][3]);
        *(float4*)&Out[(((size_t)(bb * Hh + h)) * Ss + s) * Dd + d] = v;
    }
}

// ---------------------------------------------------------------------------
// Kernel 2: causal flash attention, fp32.
// Grid: (32 q-tiles, 32 b*h).  64x64 tiles, D=64.  16x16 threads, 4x4 tiles.
// Smem: Qs (natural), KPs (K d-major, later reused for P), Vs (natural) = 48KB.
// ---------------------------------------------------------------------------
__global__ __launch_bounds__(256) void attn_kernel()
{
    __shared__ float Qs[64 * 64];   // [r][d], Q pre-scaled by D^-0.5
    __shared__ float KPs[64 * 64];  // phase 1: K^T [d][c]; phase 2: P [r][k]
    __shared__ float Vs[64 * 64];   // [k][d]

    const int tx = threadIdx.x, ty = threadIdx.y;
    const int tid = ty * 16 + tx;
    const int bh = blockIdx.y;
    const int qt = gridDim.x - 1 - blockIdx.x;  // heavy tiles first
    const int q0 = qt * 64;

    const float* Qg = g_Q + (size_t)bh * Ss * Dd;
    const float* Kg = g_K + (size_t)bh * Ss * Dd;
    const float* Vg = g_V + (size_t)bh * Ss * Dd;

    // Load Q tile, pre-scaled by 1/sqrt(64) = 0.125
#pragma unroll
    for (int t = 0; t < 4; t++) {
        int idx = t * 256 + tid;
        int r = idx >> 4;
        int d4 = (idx & 15) * 4;
        float4 q = *(const float4*)&Qg[(size_t)(q0 + r) * Dd + d4];
        q.x *= 0.125f; q.y *= 0.125f; q.z *= 0.125f; q.w *= 0.125f;
        *(float4*)&Qs[r * 64 + d4] = q;
    }

    float m_i[4], l_i[4], acc[4][4] = {};
#pragma unroll
    for (int i = 0; i < 4; i++) { m_i[i] = -1e30f; l_i[i] = 0.f; }

    for (int kt = 0; kt <= qt; kt++) {
        const int k0 = kt * 64;
        __syncthreads();  // prior PV-reads of KPs/Vs done before overwrite

        // K transposed into KPs[d][c]: global read lane-strided, STS conflict-free
#pragma unroll
        for (int t = 0; t < 4; t++) {
            int idx = t * 256 + tid;
            int c = idx & 63;
            int d4 = (idx >> 6) * 4;
            float4 kv = *(const float4*)&Kg[(size_t)(k0 + c) * Dd + d4];
            KPs[(d4 + 0) * 64 + c] = kv.x;
            KPs[(d4 + 1) * 64 + c] = kv.y;
            KPs[(d4 + 2) * 64 + c] = kv.z;
            KPs[(d4 + 3) * 64 + c] = kv.w;
        }
        // V natural layout
#pragma unroll
        for (int t = 0; t < 4; t++) {
            int idx = t * 256 + tid;
            int r = idx >> 4;
            int d4 = (idx & 15) * 4;
            float4 vv = *(const float4*)&Vg[(size_t)(k0 + r) * Dd + d4];
            *(float4*)&Vs[r * 64 + d4] = vv;
        }
        __syncthreads();

        // Scores: sc[i][j] = sum_d Q[4ty+i][d] * K[4tx+j][d]
        float sc[4][4] = {};
#pragma unroll
        for (int d4 = 0; d4 < 16; d4++) {
            float q[4][4];
#pragma unroll
            for (int i = 0; i < 4; i++) {
                float4 qv = *(const float4*)&Qs[(ty * 4 + i) * 64 + d4 * 4];
                q[i][0] = qv.x; q[i][1] = qv.y; q[i][2] = qv.z; q[i][3] = qv.w;
            }
#pragma unroll
            for (int u = 0; u < 4; u++) {
                float4 kv = *(const float4*)&KPs[(d4 * 4 + u) * 64 + tx * 4];
                float kr[4] = {kv.x, kv.y, kv.z, kv.w};
#pragma unroll
                for (int i = 0; i < 4; i++)
#pragma unroll
                    for (int j = 0; j < 4; j++)
                        sc[i][j] += q[i][u] * kr[j];
            }
        }

        // Causal mask on the diagonal tile
        if (kt == qt) {
#pragma unroll
            for (int i = 0; i < 4; i++)
#pragma unroll
                for (int j = 0; j < 4; j++)
                    if (tx * 4 + j > ty * 4 + i) sc[i][j] = -1e30f;
        }

        // Online softmax update; row spread across 16 tx lanes (within warp half)
#pragma unroll
        for (int i = 0; i < 4; i++) {
            float mrow = fmaxf(fmaxf(sc[i][0], sc[i][1]), fmaxf(sc[i][2], sc[i][3]));
#pragma unroll
            for (int off = 1; off < 16; off <<= 1)
                mrow = fmaxf(mrow, __shfl_xor_sync(0xffffffffu, mrow, off));
            float mnew = fmaxf(m_i[i], mrow);
            float corr = __expf(m_i[i] - mnew);
            m_i[i] = mnew;
            float lrow = 0.f;
#pragma unroll
            for (int j = 0; j < 4; j++) {
                sc[i][j] = __expf(sc[i][j] - mnew);
                lrow += sc[i][j];
            }
#pragma unroll
            for (int off = 1; off < 16; off <<= 1)
                lrow += __shfl_xor_sync(0xffffffffu, lrow, off);
            l_i[i] = l_i[i] * corr + lrow;
#pragma unroll
            for (int j = 0; j < 4; j++) acc[i][j] *= corr;
        }

        __syncthreads();  // everyone done reading KPs as K^T
        // Store P into KPs as [r][k]
#pragma unroll
        for (int i = 0; i < 4; i++)
            *(float4*)&KPs[(ty * 4 + i) * 64 + tx * 4] =
                make_float4(sc[i][0], sc[i][1], sc[i][2], sc[i][3]);
        __syncthreads();

        // acc[i][j] += sum_k P[4ty+i][k] * V[k][4tx+j]
#pragma unroll
        for (int k4 = 0; k4 < 16; k4++) {
            float p[4][4];
#pragma unroll
            for (int i = 0; i < 4; i++) {
                float4 pv = *(const float4*)&KPs[(ty * 4 + i) * 64 + k4 * 4];
                p[i][0] = pv.x; p[i][1] = pv.y; p[i][2] = pv.z; p[i][3] = pv.w;
            }
#pragma unroll
            for (int u = 0; u < 4; u++) {
                float4 vv = *(const float4*)&Vs[(k4 * 4 + u) * 64 + tx * 4];
                float vr[4] = {vv.x, vv.y, vv.z, vv.w};
#pragma unroll
                for (int i = 0; i < 4; i++)
#pragma unroll
                    for (int j = 0; j < 4; j++)
                        acc[i][j] += p[i][u] * vr[j];
            }
        }
    }

    // Epilogue: O = acc / l
    float* Og = g_O + (size_t)bh * Ss * Dd;
#pragma unroll
    for (int i = 0; i < 4; i++) {
        float inv = 1.0f / l_i[i];
        float4 o = make_float4(acc[i][0] * inv, acc[i][1] * inv,
                               acc[i][2] * inv, acc[i][3] * inv);
        *(float4*)&Og[(size_t)(q0 + ty * 4 + i) * Dd + tx * 4] = o;
    }
}

// ---------------------------------------------------------------------------
// Kernel 3: output projection with gather from [B,H,S,D] + bias.
// out[row, n] = sum_e O[row, e] * Wo[e, n] + bo[n]
// ---------------------------------------------------------------------------
__global__ __launch_bounds__(256) void proj_kernel(
    const float* __restrict__ Wo,
    const float* __restrict__ bo,
    float* __restrict__ out)
{
    __shared__ float As[16][68];
    __shared__ float Bs[16][64];

    const int tx = threadIdx.x, ty = threadIdx.y;
    const int tid = ty * 16 + tx;
    const int n0 = blockIdx.x * 64;
    const int m0 = blockIdx.y * 64;

    const int arow = tid >> 2;
    const int acol = (tid & 3) * 4;
    const int brow = tid >> 4;
    const int bcol = (tid & 15) * 4;

    const int row = m0 + arow;
    const int bb = row >> 11;
    const int s = row & (Ss - 1);
    // base of O[bb, :, s, :]
    const float* Abase = g_O + ((size_t)bb * Hh) * Ss * Dd + (size_t)s * Dd;
    const float* Bp = Wo + (size_t)brow * Ee + n0 + bcol;

    float acc[4][4] = {};

    for (int k0 = 0; k0 < Ee; k0 += 16) {
        int e = k0 + acol;           // 4 consecutive e within one head (16|64)
        int h = e >> 6;
        int d = e & 63;
        float4 a = *(const float4*)(Abase + (size_t)h * Ss * Dd + d);
        float4 b = *(const float4*)(Bp + (size_t)k0 * Ee);
        As[acol + 0][arow] = a.x;
        As[acol + 1][arow] = a.y;
        As[acol + 2][arow] = a.z;
        As[acol + 3][arow] = a.w;
        *(float4*)&Bs[brow][bcol] = b;
        __syncthreads();
#pragma unroll
        for (int kk = 0; kk < 16; kk++) {
            float4 av = *(const float4*)&As[kk][ty * 4];
            float4 bv = *(const float4*)&Bs[kk][tx * 4];
            float ar[4] = {av.x, av.y, av.z, av.w};
            float br[4] = {bv.x, bv.y, bv.z, bv.w};
#pragma unroll
            for (int i = 0; i < 4; i++)
#pragma unroll
                for (int j = 0; j < 4; j++)
                    acc[i][j] += ar[i] * br[j];
        }
        __syncthreads();
    }

    float4 bias = *(const float4*)&bo[n0 + tx * 4];
    float br[4] = {bias.x, bias.y, bias.z, bias.w};
#pragma unroll
    for (int i = 0; i < 4; i++) {
        int r = m0 + ty * 4 + i;
        float4 v = make_float4(acc[i][0] + br[0], acc[i][1] + br[1],
                               acc[i][2] + br[2], acc[i][3] + br[3]);
        *(float4*)&out[(size_t)r * Ee + n0 + tx * 4] = v;
    }
}

// ---------------------------------------------------------------------------
extern "C" void kernel_launch(void* const* d_in, const int* in_sizes, int n_in,
                              void* d_out, int out_size)
{
    const float* x  = (const float*)d_in[0];
    const float* Wq = (const float*)d_in[1];
    const float* Wk = (const float*)d_in[2];
    const float* Wv = (const float*)d_in[3];
    const float* Wo = (const float*)d_in[4];
    const float* bo = (const float*)d_in[5];
    float* out = (float*)d_out;

    dim3 blk(16, 16);
    qkv_kernel<<<dim3(16, 64, 3), blk>>>(x, Wq, Wk, Wv);
    attn_kernel<<<dim3(32, 32), blk>>>();
    proj_kernel<<<dim3(16, 64), blk>>>(Wo, bo, out);
}

// round 4
// speedup vs baseline: 2.1746x; 2.1746x over previous
#include <cuda_runtime.h>
#include <cuda_bf16.h>
#include <cstdint>

#define Ss 2048
#define Ee 1024
#define Hh 16
#define Dd 64
// 32 bh heads-batches, 4096 total rows

// ---------------- device scratch (bf16 hi/lo everywhere) -------------------
__device__ __nv_bfloat16 g_xhi[(size_t)4096 * 1024];
__device__ __nv_bfloat16 g_xlo[(size_t)4096 * 1024];
__device__ __nv_bfloat16 g_wThi[(size_t)4 * 1024 * 1024];   // [mat][n][k]
__device__ __nv_bfloat16 g_wTlo[(size_t)4 * 1024 * 1024];
__device__ __nv_bfloat16 g_Qhi[(size_t)32 * Ss * Dd];       // [bh][s][d] (pre-scaled)
__device__ __nv_bfloat16 g_Qlo[(size_t)32 * Ss * Dd];
__device__ __nv_bfloat16 g_Khi[(size_t)32 * Ss * Dd];
__device__ __nv_bfloat16 g_Klo[(size_t)32 * Ss * Dd];
__device__ __nv_bfloat16 g_Vhi[(size_t)32 * Ss * Dd];
__device__ __nv_bfloat16 g_Vlo[(size_t)32 * Ss * Dd];
__device__ __nv_bfloat16 g_Vthi[(size_t)32 * Dd * Ss];      // [bh][d][s]
__device__ __nv_bfloat16 g_Vtlo[(size_t)32 * Dd * Ss];
__device__ __nv_bfloat16 g_Ohi[(size_t)4096 * 1024];        // [b*S+s][h*64+d]
__device__ __nv_bfloat16 g_Olo[(size_t)4096 * 1024];

// ---------------- helpers --------------------------------------------------
__device__ __forceinline__ void mma_bf16(float c[4],
                                         uint32_t a0, uint32_t a1, uint32_t a2, uint32_t a3,
                                         uint32_t b0, uint32_t b1) {
    asm volatile(
        "mma.sync.aligned.m16n8k16.row.col.f32.bf16.bf16.f32 "
        "{%0,%1,%2,%3},{%4,%5,%6,%7},{%8,%9},{%0,%1,%2,%3};"
        : "+f"(c[0]), "+f"(c[1]), "+f"(c[2]), "+f"(c[3])
        : "r"(a0), "r"(a1), "r"(a2), "r"(a3), "r"(b0), "r"(b1));
}
__device__ __forceinline__ uint32_t ld32(const __nv_bfloat16* p) {
    return *(const uint32_t*)p;
}
__device__ __forceinline__ void split2(float v, __nv_bfloat16& h, __nv_bfloat16& l) {
    h = __float2bfloat16(v);
    l = __float2bfloat16(v - __bfloat162float(h));
}

// ===========================================================================
// Pre-pass: split x into hi/lo bf16
// ===========================================================================
__global__ __launch_bounds__(256) void split_x(const float* __restrict__ src) {
    int i = blockIdx.x * 256 + threadIdx.x;
    float v = src[i];
    __nv_bfloat16 h, l;
    split2(v, h, l);
    g_xhi[i] = h;
    g_xlo[i] = l;
}

// Pre-pass: transpose + split weights: g_wT[z][n][k] = W_z[k][n]
__global__ __launch_bounds__(256) void wsplit(
    const float* __restrict__ Wq, const float* __restrict__ Wk,
    const float* __restrict__ Wv, const float* __restrict__ Wo)
{
    __shared__ float t[32][33];
    const int z = blockIdx.z;
    const float* W = (z == 0) ? Wq : (z == 1) ? Wk : (z == 2) ? Wv : Wo;
    const int tx = threadIdx.x, ty = threadIdx.y;   // (32,8)
    const int bx = blockIdx.x, by = blockIdx.y;
#pragma unroll
    for (int i = 0; i < 32; i += 8)
        t[ty + i][tx] = W[(size_t)(by * 32 + ty + i) * Ee + bx * 32 + tx];
    __syncthreads();
    const size_t base = (size_t)z * Ee * Ee;
#pragma unroll
    for (int i = 0; i < 32; i += 8) {
        int n = bx * 32 + ty + i, k = by * 32 + tx;
        __nv_bfloat16 h, l;
        split2(t[tx][ty + i], h, l);
        g_wThi[base + (size_t)n * Ee + k] = h;
        g_wTlo[base + (size_t)n * Ee + k] = l;
    }
}

// Pre-pass: V transpose per head: g_Vt[bh][d][s] = g_V[bh][s][d] (hi & lo)
__global__ __launch_bounds__(256) void vtrans() {
    __shared__ __nv_bfloat16 t[32][33];
    const int bh = blockIdx.z >> 1, tile = blockIdx.z & 1;
    const __nv_bfloat16* src = (tile ? g_Vlo : g_Vhi) + (size_t)bh * Ss * Dd;
    __nv_bfloat16* dst = (tile ? g_Vtlo : g_Vthi) + (size_t)bh * Dd * Ss;
    const int tx = threadIdx.x, ty = threadIdx.y;   // (32,8)
    const int s0 = blockIdx.x * 32, d0 = blockIdx.y * 32;
#pragma unroll
    for (int i = 0; i < 32; i += 8)
        t[ty + i][tx] = src[(size_t)(s0 + ty + i) * Dd + d0 + tx];
    __syncthreads();
#pragma unroll
    for (int i = 0; i < 32; i += 8)
        dst[(size_t)(d0 + ty + i) * Ss + s0 + tx] = t[tx][ty + i];
}

// ===========================================================================
// Compensated-bf16 GEMM (QKV / proj), mma.sync m16n8k16.
// 256 thr (8 warps), tile 128x128, Kc=32 chunks, warp tile 64x32.
// Smem tiles [row][k] bf16, pitch 40 bf16 (20 words; 20 mod 32 -> frag LDS
// pattern g*20+t4 hits 32 distinct banks).
// ===========================================================================
#define GP 40
#define G_AH 0
#define G_AL 5120
#define G_BH 10240
#define G_BL 15360

struct GemmAcc { float a[4][4][4]; };

__device__ __forceinline__ void gemm128_mainloop(
    const __nv_bfloat16* __restrict__ Ah_g, const __nv_bfloat16* __restrict__ Al_g,
    const __nv_bfloat16* __restrict__ Bh_g, const __nv_bfloat16* __restrict__ Bl_g,
    __nv_bfloat16* sm, GemmAcc& C)
{
    const int tid = threadIdx.x;
    const int wid = tid >> 5, lane = tid & 31;
    const int g = lane >> 2, t4 = lane & 3;
    const int wm = (wid & 1) * 64, wn = (wid >> 1) * 32;
    const int r0 = tid >> 2, c0 = (tid & 3) * 8;   // slot rows r0, r0+64

    uint4 rAh[2], rAl[2], rBh[2], rBl[2];
#pragma unroll
    for (int j = 0; j < 2; j++) {
        size_t go = (size_t)(r0 + j * 64) * Ee + c0;
        rAh[j] = *(const uint4*)(Ah_g + go);
        rAl[j] = *(const uint4*)(Al_g + go);
        rBh[j] = *(const uint4*)(Bh_g + go);
        rBl[j] = *(const uint4*)(Bl_g + go);
    }

    for (int kc = 0; kc < 32; kc++) {
#pragma unroll
        for (int j = 0; j < 2; j++) {
            int si = (r0 + j * 64) * GP + c0;
            *(uint4*)(sm + G_AH + si) = rAh[j];
            *(uint4*)(sm + G_AL + si) = rAl[j];
            *(uint4*)(sm + G_BH + si) = rBh[j];
            *(uint4*)(sm + G_BL + si) = rBl[j];
        }
        __syncthreads();

        if (kc < 31) {
            int k0n = (kc + 1) * 32;
#pragma unroll
            for (int j = 0; j < 2; j++) {
                size_t go = (size_t)(r0 + j * 64) * Ee + k0n + c0;
                rAh[j] = *(const uint4*)(Ah_g + go);
                rAl[j] = *(const uint4*)(Al_g + go);
                rBh[j] = *(const uint4*)(Bh_g + go);
                rBl[j] = *(const uint4*)(Bl_g + go);
            }
        }

#pragma unroll
        for (int ks = 0; ks < 2; ks++) {
            uint32_t ah[4][4], al[4][4];
#pragma unroll
            for (int mf = 0; mf < 4; mf++) {
                int base = (wm + mf * 16 + g) * GP + ks * 16 + 2 * t4;
                ah[mf][0] = ld32(sm + G_AH + base);
                ah[mf][1] = ld32(sm + G_AH + base + 8 * GP);
                ah[mf][2] = ld32(sm + G_AH + base + 8);
                ah[mf][3] = ld32(sm + G_AH + base + 8 * GP + 8);
                al[mf][0] = ld32(sm + G_AL + base);
                al[mf][1] = ld32(sm + G_AL + base + 8 * GP);
                al[mf][2] = ld32(sm + G_AL + base + 8);
                al[mf][3] = ld32(sm + G_AL + base + 8 * GP + 8);
            }
#pragma unroll
            for (int nf = 0; nf < 4; nf++) {
                int bi = (wn + nf * 8 + g) * GP + ks * 16 + 2 * t4;
                uint32_t bh0 = ld32(sm + G_BH + bi), bh1 = ld32(sm + G_BH + bi + 8);
                uint32_t bl0 = ld32(sm + G_BL + bi), bl1 = ld32(sm + G_BL + bi + 8);
#pragma unroll
                for (int mf = 0; mf < 4; mf++) {
                    mma_bf16(C.a[mf][nf], ah[mf][0], ah[mf][1], ah[mf][2], ah[mf][3], bh0, bh1);
                    mma_bf16(C.a[mf][nf], ah[mf][0], ah[mf][1], ah[mf][2], ah[mf][3], bl0, bl1);
                    mma_bf16(C.a[mf][nf], al[mf][0], al[mf][1], al[mf][2], al[mf][3], bh0, bh1);
                }
            }
        }
        __syncthreads();
    }
}

// ---- QKV: x @ W_z -> Q/K/V hi/lo bf16 in [bh][s][d]; Q pre-scaled 0.125 ---
__global__ __launch_bounds__(256) void gemm_qkv() {
    __shared__ __nv_bfloat16 sm[20480];
    const int tid = threadIdx.x;
    const int wid = tid >> 5, lane = tid & 31;
    const int g = lane >> 2, t4 = lane & 3;
    const int wm = (wid & 1) * 64, wn = (wid >> 1) * 32;
    const int n0 = blockIdx.x * 128, m0 = blockIdx.y * 128, z = blockIdx.z;

    GemmAcc C = {};
    gemm128_mainloop(g_xhi + (size_t)m0 * Ee, g_xlo + (size_t)m0 * Ee,
                     g_wThi + ((size_t)z * Ee + n0) * Ee,
                     g_wTlo + ((size_t)z * Ee + n0) * Ee, sm, C);

    const float qs = (z == 0) ? 0.125f : 1.0f;
    __nv_bfloat16* Oh = (z == 0) ? g_Qhi : (z == 1) ? g_Khi : g_Vhi;
    __nv_bfloat16* Ol = (z == 0) ? g_Qlo : (z == 1) ? g_Klo : g_Vlo;

#pragma unroll
    for (int mf = 0; mf < 4; mf++)
#pragma unroll
        for (int nf = 0; nf < 4; nf++) {
            int col = n0 + wn + nf * 8 + t4 * 2;
            int h = col >> 6, d = col & 63;
#pragma unroll
            for (int half = 0; half < 2; half++) {
                int row = m0 + wm + mf * 16 + g + half * 8;
                int b = row >> 11, s = row & (Ss - 1);
                size_t di = (((size_t)(b * Hh + h)) * Ss + s) * Dd + d;
                __nv_bfloat16 h0, l0, h1, l1;
                split2(C.a[mf][nf][half * 2] * qs, h0, l0);
                split2(C.a[mf][nf][half * 2 + 1] * qs, h1, l1);
                *(__nv_bfloat162*)&Oh[di] = __nv_bfloat162(h0, h1);
                *(__nv_bfloat162*)&Ol[di] = __nv_bfloat162(l0, l1);
            }
        }
}

// ---- proj: O @ Wo + bo -> fp32 out ---------------------------------------
__global__ __launch_bounds__(256) void gemm_proj(const float* __restrict__ bo,
                                                 float* __restrict__ out) {
    __shared__ __nv_bfloat16 sm[20480];
    const int tid = threadIdx.x;
    const int wid = tid >> 5, lane = tid & 31;
    const int g = lane >> 2, t4 = lane & 3;
    const int wm = (wid & 1) * 64, wn = (wid >> 1) * 32;
    const int n0 = blockIdx.x * 128, m0 = blockIdx.y * 128;

    GemmAcc C = {};
    gemm128_mainloop(g_Ohi + (size_t)m0 * Ee, g_Olo + (size_t)m0 * Ee,
                     g_wThi + ((size_t)3 * Ee + n0) * Ee,
                     g_wTlo + ((size_t)3 * Ee + n0) * Ee, sm, C);

#pragma unroll
    for (int mf = 0; mf < 4; mf++)
#pragma unroll
        for (int nf = 0; nf < 4; nf++) {
            int col = n0 + wn + nf * 8 + t4 * 2;
            float2 bias = *(const float2*)&bo[col];
#pragma unroll
            for (int half = 0; half < 2; half++) {
                int row = m0 + wm + mf * 16 + g + half * 8;
                *(float2*)&out[(size_t)row * Ee + col] =
                    make_float2(C.a[mf][nf][half * 2] + bias.x,
                                C.a[mf][nf][half * 2 + 1] + bias.y);
            }
        }
}

// ===========================================================================
// Attention: compensated-bf16 mma flash attention.
// 128 thr (4 warps), q-tile 128 rows (32/warp), k-tiles 64.
// Smem bf16 pitch 72 (36 words; 36 mod 32 = 4 -> conflict-free frag LDS).
// ===========================================================================
#define AP2 72
#define A_QH 0
#define A_QL 9216
#define A_KH 18432
#define A_KL 23040
#define A_VH 27648
#define A_VL 32256
#define A_PH 36864
#define A_PL 46080
#define ATTN_SMEM (55296 * 2)

__global__ __launch_bounds__(128) void attn_bf16() {
    extern __shared__ __nv_bfloat16 sm[];
    const int tid = threadIdx.x;
    const int wid = tid >> 5, lane = tid & 31;
    const int g = lane >> 2, t4 = lane & 3;
    const int bh = blockIdx.y;
    const int qb = gridDim.x - 1 - blockIdx.x;    // heavy tiles first
    const int q0 = qb * 128;
    const int wrow = wid * 32;

    const __nv_bfloat16* Qh_g = g_Qhi + (size_t)bh * Ss * Dd;
    const __nv_bfloat16* Ql_g = g_Qlo + (size_t)bh * Ss * Dd;
    const __nv_bfloat16* Kh_g = g_Khi + (size_t)bh * Ss * Dd;
    const __nv_bfloat16* Kl_g = g_Klo + (size_t)bh * Ss * Dd;
    const __nv_bfloat16* Vh_g = g_Vthi + (size_t)bh * Dd * Ss;
    const __nv_bfloat16* Vl_g = g_Vtlo + (size_t)bh * Dd * Ss;

    // stage Q hi/lo: 128x64
#pragma unroll
    for (int t = 0; t < 16; t++) {
        int slot = t * 128 + tid;
        int tile = slot >> 10, s2 = slot & 1023;
        int r = s2 >> 3, c = (s2 & 7) * 8;
        const __nv_bfloat16* src = (tile ? Ql_g : Qh_g) + (size_t)(q0 + r) * Dd + c;
        *(uint4*)(sm + (tile ? A_QL : A_QH) + r * AP2 + c) = *(const uint4*)src;
    }

    float m_i[4], l_i[4], o[2][8][4] = {};
#pragma unroll
    for (int i = 0; i < 4; i++) { m_i[i] = -1e30f; l_i[i] = 0.f; }

    const int ktmax = 2 * qb + 2;
    for (int kt = 0; kt < ktmax; kt++) {
        const int k0 = kt * 64;
        __syncthreads();
        // stage K hi/lo [64 rows][64 d] and Vt hi/lo [64 d][64 s]
#pragma unroll
        for (int t = 0; t < 8; t++) {
            int slot = t * 128 + tid;
            int tile = slot >> 9, s2 = slot & 511;
            int r = s2 >> 3, c = (s2 & 7) * 8;
            *(uint4*)(sm + (tile ? A_KL : A_KH) + r * AP2 + c) =
                *(const uint4*)((tile ? Kl_g : Kh_g) + (size_t)(k0 + r) * Dd + c);
            *(uint4*)(sm + (tile ? A_VL : A_VH) + r * AP2 + c) =
                *(const uint4*)((tile ? Vl_g : Vh_g) + (size_t)r * Ss + k0 + c);
        }
        __syncthreads();

        // ---- S = Q K^T (compensated) ----
        float sc[2][8][4] = {};
#pragma unroll
        for (int ks = 0; ks < 4; ks++) {
            uint32_t ah[2][4], al[2][4];
#pragma unroll
            for (int mf = 0; mf < 2; mf++) {
                int base = (wrow + mf * 16 + g) * AP2 + ks * 16 + 2 * t4;
                ah[mf][0] = ld32(sm + A_QH + base);
                ah[mf][1] = ld32(sm + A_QH + base + 8 * AP2);
                ah[mf][2] = ld32(sm + A_QH + base + 8);
                ah[mf][3] = ld32(sm + A_QH + base + 8 * AP2 + 8);
                al[mf][0] = ld32(sm + A_QL + base);
                al[mf][1] = ld32(sm + A_QL + base + 8 * AP2);
                al[mf][2] = ld32(sm + A_QL + base + 8);
                al[mf][3] = ld32(sm + A_QL + base + 8 * AP2 + 8);
            }
#pragma unroll
            for (int nf = 0; nf < 8; nf++) {
                int bi = (nf * 8 + g) * AP2 + ks * 16 + 2 * t4;
                uint32_t bh0 = ld32(sm + A_KH + bi), bh1 = ld32(sm + A_KH + bi + 8);
                uint32_t bl0 = ld32(sm + A_KL + bi), bl1 = ld32(sm + A_KL + bi + 8);
#pragma unroll
                for (int mf = 0; mf < 2; mf++) {
                    mma_bf16(sc[mf][nf], ah[mf][0], ah[mf][1], ah[mf][2], ah[mf][3], bh0, bh1);
                    mma_bf16(sc[mf][nf], ah[mf][0], ah[mf][1], ah[mf][2], ah[mf][3], bl0, bl1);
                    mma_bf16(sc[mf][nf], al[mf][0], al[mf][1], al[mf][2], al[mf][3], bh0, bh1);
                }
            }
        }

        // ---- causal mask (last two k-tiles of this q-block) ----
        if (kt >= 2 * qb) {
#pragma unroll
            for (int mf = 0; mf < 2; mf++)
#pragma unroll
                for (int nf = 0; nf < 8; nf++)
#pragma unroll
                    for (int j = 0; j < 4; j++) {
                        int col = k0 + nf * 8 + t4 * 2 + (j & 1);
                        int row = q0 + wrow + mf * 16 + g + (j >> 1) * 8;
                        if (col > row) sc[mf][nf][j] = -1e30f;
                    }
        }

        // ---- online softmax (rows spread over 4-lane groups) ----
#pragma unroll
        for (int mf = 0; mf < 2; mf++) {
#pragma unroll
            for (int half = 0; half < 2; half++) {
                const int j0 = half * 2;
                float mrow = -1e30f;
#pragma unroll
                for (int nf = 0; nf < 8; nf++)
                    mrow = fmaxf(mrow, fmaxf(sc[mf][nf][j0], sc[mf][nf][j0 + 1]));
                mrow = fmaxf(mrow, __shfl_xor_sync(0xffffffffu, mrow, 1));
                mrow = fmaxf(mrow, __shfl_xor_sync(0xffffffffu, mrow, 2));
                const int li = mf * 2 + half;
                float mnew = fmaxf(m_i[li], mrow);
                float corr = __expf(m_i[li] - mnew);
                m_i[li] = mnew;
                float ps = 0.f;
#pragma unroll
                for (int nf = 0; nf < 8; nf++) {
                    float e0 = __expf(sc[mf][nf][j0] - mnew);
                    float e1 = __expf(sc[mf][nf][j0 + 1] - mnew);
                    sc[mf][nf][j0] = e0; sc[mf][nf][j0 + 1] = e1;
                    ps += e0 + e1;
                }
                ps += __shfl_xor_sync(0xffffffffu, ps, 1);
                ps += __shfl_xor_sync(0xffffffffu, ps, 2);
                l_i[li] = l_i[li] * corr + ps;
#pragma unroll
                for (int nf = 0; nf < 8; nf++) {
                    o[mf][nf][j0] *= corr;
                    o[mf][nf][j0 + 1] *= corr;
                }
            }
        }

        // ---- P -> smem hi/lo (warp-private rows) ----
#pragma unroll
        for (int mf = 0; mf < 2; mf++)
#pragma unroll
            for (int nf = 0; nf < 8; nf++) {
                int row0 = wrow + mf * 16 + g;
                int col = nf * 8 + t4 * 2;
                __nv_bfloat16 h0, l0, h1, l1;
                split2(sc[mf][nf][0], h0, l0);
                split2(sc[mf][nf][1], h1, l1);
                *(__nv_bfloat162*)(sm + A_PH + row0 * AP2 + col) = __nv_bfloat162(h0, h1);
                *(__nv_bfloat162*)(sm + A_PL + row0 * AP2 + col) = __nv_bfloat162(l0, l1);
                split2(sc[mf][nf][2], h0, l0);
                split2(sc[mf][nf][3], h1, l1);
                *(__nv_bfloat162*)(sm + A_PH + (row0 + 8) * AP2 + col) = __nv_bfloat162(h0, h1);
                *(__nv_bfloat162*)(sm + A_PL + (row0 + 8) * AP2 + col) = __nv_bfloat162(l0, l1);
            }
        __syncwarp();

        // ---- O += P V (compensated) ----
#pragma unroll
        for (int ks = 0; ks < 4; ks++) {
            uint32_t ah[2][4], al[2][4];
#pragma unroll
            for (int mf = 0; mf < 2; mf++) {
                int base = (wrow + mf * 16 + g) * AP2 + ks * 16 + 2 * t4;
                ah[mf][0] = ld32(sm + A_PH + base);
                ah[mf][1] = ld32(sm + A_PH + base + 8 * AP2);
                ah[mf][2] = ld32(sm + A_PH + base + 8);
                ah[mf][3] = ld32(sm + A_PH + base + 8 * AP2 + 8);
                al[mf][0] = ld32(sm + A_PL + base);
                al[mf][1] = ld32(sm + A_PL + base + 8 * AP2);
                al[mf][2] = ld32(sm + A_PL + base + 8);
                al[mf][3] = ld32(sm + A_PL + base + 8 * AP2 + 8);
            }
#pragma unroll
            for (int nf = 0; nf < 8; nf++) {
                int bi = (nf * 8 + g) * AP2 + ks * 16 + 2 * t4;
                uint32_t bh0 = ld32(sm + A_VH + bi), bh1 = ld32(sm + A_VH + bi + 8);
                uint32_t bl0 = ld32(sm + A_VL + bi), bl1 = ld32(sm + A_VL + bi + 8);
#pragma unroll
                for (int mf = 0; mf < 2; mf++) {
                    mma_bf16(o[mf][nf], ah[mf][0], ah[mf][1], ah[mf][2], ah[mf][3], bh0, bh1);
                    mma_bf16(o[mf][nf], ah[mf][0], ah[mf][1], ah[mf][2], ah[mf][3], bl0, bl1);
                    mma_bf16(o[mf][nf], al[mf][0], al[mf][1], al[mf][2], al[mf][3], bh0, bh1);
                }
            }
        }
    }

    // ---- epilogue: O/l -> hi/lo bf16 in proj layout [b*S+s][h*64+d] ----
    const int b = bh >> 4, h = bh & 15;
#pragma unroll
    for (int mf = 0; mf < 2; mf++) {
        float inv_lo = 1.0f / l_i[mf * 2];
        float inv_hi = 1.0f / l_i[mf * 2 + 1];
#pragma unroll
        for (int nf = 0; nf < 8; nf++) {
            int srow = q0 + wrow + mf * 16 + g;
            int col = h * 64 + nf * 8 + t4 * 2;
            size_t r0i = ((size_t)b * Ss + srow) * Ee + col;
            size_t r1i = ((size_t)b * Ss + srow + 8) * Ee + col;
            __nv_bfloat16 h0, l0, h1, l1;
            split2(o[mf][nf][0] * inv_lo, h0, l0);
            split2(o[mf][nf][1] * inv_lo, h1, l1);
            *(__nv_bfloat162*)&g_Ohi[r0i] = __nv_bfloat162(h0, h1);
            *(__nv_bfloat162*)&g_Olo[r0i] = __nv_bfloat162(l0, l1);
            split2(o[mf][nf][2] * inv_hi, h0, l0);
            split2(o[mf][nf][3] * inv_hi, h1, l1);
            *(__nv_bfloat162*)&g_Ohi[r1i] = __nv_bfloat162(h0, h1);
            *(__nv_bfloat162*)&g_Olo[r1i] = __nv_bfloat162(l0, l1);
        }
    }
}

// ---------------------------------------------------------------------------
extern "C" void kernel_launch(void* const* d_in, const int* in_sizes, int n_in,
                              void* d_out, int out_size)
{
    const float* x  = (const float*)d_in[0];
    const float* Wq = (const float*)d_in[1];
    const float* Wk = (const float*)d_in[2];
    const float* Wv = (const float*)d_in[3];
    const float* Wo = (const float*)d_in[4];
    const float* bo = (const float*)d_in[5];
    float* out = (float*)d_out;

    cudaFuncSetAttribute(attn_bf16, cudaFuncAttributeMaxDynamicSharedMemorySize, ATTN_SMEM);

    split_x<<<16384, 256>>>(x);
    wsplit<<<dim3(32, 32, 4), dim3(32, 8)>>>(Wq, Wk, Wv, Wo);
    gemm_qkv<<<dim3(8, 32, 3), 256>>>();
    vtrans<<<dim3(64, 2, 64), dim3(32, 8)>>>();
    attn_bf16<<<dim3(16, 32), 128, ATTN_SMEM>>>();
    gemm_proj<<<dim3(8, 32), 256>>>(bo, out);
}

// round 6
// speedup vs baseline: 2.2065x; 1.0147x over previous
#include <cuda_runtime.h>
#include <cuda_bf16.h>
#include <cstdint>

#define Ss 2048
#define Ee 1024
#define Hh 16
#define Dd 64

// ---------------- device scratch ------------------------------------------
__device__ __nv_bfloat16 g_xhi[(size_t)4096 * 1024];
__device__ __nv_bfloat16 g_xlo[(size_t)4096 * 1024];
__device__ __nv_bfloat16 g_wThi[(size_t)4 * 1024 * 1024];   // [mat][n][k]
__device__ __nv_bfloat16 g_wTlo[(size_t)4 * 1024 * 1024];
__device__ __nv_bfloat16 g_Qhi[(size_t)32 * Ss * Dd];       // [bh][s][d] pre-scaled
__device__ __nv_bfloat16 g_Qlo[(size_t)32 * Ss * Dd];
__device__ __nv_bfloat16 g_Khi[(size_t)32 * Ss * Dd];
__device__ __nv_bfloat16 g_Klo[(size_t)32 * Ss * Dd];
__device__ __nv_bfloat16 g_Vhi[(size_t)32 * Ss * Dd];
__device__ __nv_bfloat16 g_Vlo[(size_t)32 * Ss * Dd];
__device__ __nv_bfloat16 g_Vthi[(size_t)32 * Dd * Ss];      // [bh][d][s]
__device__ __nv_bfloat16 g_Vtlo[(size_t)32 * Dd * Ss];
__device__ __nv_bfloat16 g_Ohi[(size_t)4096 * 1024];        // [b*S+s][h*64+d]
__device__ __nv_bfloat16 g_Olo[(size_t)4096 * 1024];

// ---------------- helpers --------------------------------------------------
__device__ __forceinline__ void mma_bf16(float c[4],
                                         const uint32_t a[4],
                                         uint32_t b0, uint32_t b1) {
    asm volatile(
        "mma.sync.aligned.m16n8k16.row.col.f32.bf16.bf16.f32 "
        "{%0,%1,%2,%3},{%4,%5,%6,%7},{%8,%9},{%0,%1,%2,%3};"
        : "+f"(c[0]), "+f"(c[1]), "+f"(c[2]), "+f"(c[3])
        : "r"(a[0]), "r"(a[1]), "r"(a[2]), "r"(a[3]), "r"(b0), "r"(b1));
}
__device__ __forceinline__ uint32_t lds_addr(const void* p) {
    return (uint32_t)__cvta_generic_to_shared(p);
}
__device__ __forceinline__ void ldsm4(uint32_t r[4], uint32_t a) {
    asm volatile("ldmatrix.sync.aligned.m8n8.x4.shared.b16 {%0,%1,%2,%3}, [%4];"
        : "=r"(r[0]), "=r"(r[1]), "=r"(r[2]), "=r"(r[3]) : "r"(a));
}
__device__ __forceinline__ void split2(float v, __nv_bfloat16& h, __nv_bfloat16& l) {
    h = __float2bfloat16(v);
    l = __float2bfloat16(v - __bfloat162float(h));
}

// ===========================================================================
// Pre-passes
// ===========================================================================
__global__ __launch_bounds__(256) void split_x(const float* __restrict__ src) {
    int i = blockIdx.x * 256 + threadIdx.x;
    float v = src[i];
    __nv_bfloat16 h, l;
    split2(v, h, l);
    g_xhi[i] = h;
    g_xlo[i] = l;
}

__global__ __launch_bounds__(256) void wsplit(
    const float* __restrict__ Wq, const float* __restrict__ Wk,
    const float* __restrict__ Wv, const float* __restrict__ Wo)
{
    __shared__ float t[32][33];
    const int z = blockIdx.z;
    const float* W = (z == 0) ? Wq : (z == 1) ? Wk : (z == 2) ? Wv : Wo;
    const int tx = threadIdx.x, ty = threadIdx.y;
    const int bx = blockIdx.x, by = blockIdx.y;
#pragma unroll
    for (int i = 0; i < 32; i += 8)
        t[ty + i][tx] = W[(size_t)(by * 32 + ty + i) * Ee + bx * 32 + tx];
    __syncthreads();
    const size_t base = (size_t)z * Ee * Ee;
#pragma unroll
    for (int i = 0; i < 32; i += 8) {
        int n = bx * 32 + ty + i, k = by * 32 + tx;
        __nv_bfloat16 h, l;
        split2(t[tx][ty + i], h, l);
        g_wThi[base + (size_t)n * Ee + k] = h;
        g_wTlo[base + (size_t)n * Ee + k] = l;
    }
}

__global__ __launch_bounds__(256) void vtrans() {
    __shared__ __nv_bfloat16 t[32][33];
    const int bh = blockIdx.z >> 1, tile = blockIdx.z & 1;
    const __nv_bfloat16* src = (tile ? g_Vlo : g_Vhi) + (size_t)bh * Ss * Dd;
    __nv_bfloat16* dst = (tile ? g_Vtlo : g_Vthi) + (size_t)bh * Dd * Ss;
    const int tx = threadIdx.x, ty = threadIdx.y;
    const int s0 = blockIdx.x * 32, d0 = blockIdx.y * 32;
#pragma unroll
    for (int i = 0; i < 32; i += 8)
        t[ty + i][tx] = src[(size_t)(s0 + ty + i) * Dd + d0 + tx];
    __syncthreads();
#pragma unroll
    for (int i = 0; i < 32; i += 8)
        dst[(size_t)(d0 + ty + i) * Ss + s0 + tx] = t[tx][ty + i];
}

// ===========================================================================
// Compensated-bf16 GEMM (QKV / proj), ldmatrix fragment loads.
// 256 thr, tile 128x128, 32 K-chunks of 32. Pitch 40 bf16 (conflict-free).
// ===========================================================================
#define GP 40
#define G_AH 0
#define G_AL 5120
#define G_BH 10240
#define G_BL 15360

struct GemmAcc { float a[4][4][4]; };

__device__ __forceinline__ void gemm128_mainloop(
    const __nv_bfloat16* __restrict__ Ah_g, const __nv_bfloat16* __restrict__ Al_g,
    const __nv_bfloat16* __restrict__ Bh_g, const __nv_bfloat16* __restrict__ Bl_g,
    __nv_bfloat16* sm, GemmAcc& C)
{
    const int tid = threadIdx.x;
    const int wid = tid >> 5, lane = tid & 31;
    const int grp = lane >> 3, rr = lane & 7;
    const int wm = (wid & 1) * 64, wn = (wid >> 1) * 32;
    const int r0 = tid >> 2, c0 = (tid & 3) * 8;

    uint4 rAh[2], rAl[2], rBh[2], rBl[2];
#pragma unroll
    for (int j = 0; j < 2; j++) {
        size_t go = (size_t)(r0 + j * 64) * Ee + c0;
        rAh[j] = *(const uint4*)(Ah_g + go);
        rAl[j] = *(const uint4*)(Al_g + go);
        rBh[j] = *(const uint4*)(Bh_g + go);
        rBl[j] = *(const uint4*)(Bl_g + go);
    }

    // precomputed ldmatrix lane addresses (relative to tile bases)
    const int aoff = (wm + (grp & 1) * 8 + rr) * GP + (grp >> 1) * 8;
    const int boff = (wn + rr) * GP + grp * 8;

    for (int kc = 0; kc < 32; kc++) {
#pragma unroll
        for (int j = 0; j < 2; j++) {
            int si = (r0 + j * 64) * GP + c0;
            *(uint4*)(sm + G_AH + si) = rAh[j];
            *(uint4*)(sm + G_AL + si) = rAl[j];
            *(uint4*)(sm + G_BH + si) = rBh[j];
            *(uint4*)(sm + G_BL + si) = rBl[j];
        }
        __syncthreads();

        if (kc < 31) {
            int k0n = (kc + 1) * 32;
#pragma unroll
            for (int j = 0; j < 2; j++) {
                size_t go = (size_t)(r0 + j * 64) * Ee + k0n + c0;
                rAh[j] = *(const uint4*)(Ah_g + go);
                rAl[j] = *(const uint4*)(Al_g + go);
                rBh[j] = *(const uint4*)(Bh_g + go);
                rBl[j] = *(const uint4*)(Bl_g + go);
            }
        }

        // B frags: x4 covers both ks steps {b0k0,b1k0,b0k1,b1k1}
        uint32_t bhf[4][4], blf[4][4];
#pragma unroll
        for (int nf = 0; nf < 4; nf++) {
            ldsm4(bhf[nf], lds_addr(sm + G_BH + boff + nf * 8 * GP));
            ldsm4(blf[nf], lds_addr(sm + G_BL + boff + nf * 8 * GP));
        }
#pragma unroll
        for (int ks = 0; ks < 2; ks++) {
            uint32_t ahf[4][4], alf[4][4];
#pragma unroll
            for (int mf = 0; mf < 4; mf++) {
                ldsm4(ahf[mf], lds_addr(sm + G_AH + aoff + mf * 16 * GP + ks * 16));
                ldsm4(alf[mf], lds_addr(sm + G_AL + aoff + mf * 16 * GP + ks * 16));
            }
#pragma unroll
            for (int nf = 0; nf < 4; nf++) {
                uint32_t bh0 = bhf[nf][ks * 2], bh1 = bhf[nf][ks * 2 + 1];
                uint32_t bl0 = blf[nf][ks * 2], bl1 = blf[nf][ks * 2 + 1];
#pragma unroll
                for (int mf = 0; mf < 4; mf++) {
                    mma_bf16(C.a[mf][nf], ahf[mf], bh0, bh1);
                    mma_bf16(C.a[mf][nf], ahf[mf], bl0, bl1);
                    mma_bf16(C.a[mf][nf], alf[mf], bh0, bh1);
                }
            }
        }
        __syncthreads();
    }
}

__global__ __launch_bounds__(256) void gemm_qkv() {
    __shared__ __nv_bfloat16 sm[20480];
    const int tid = threadIdx.x;
    const int wid = tid >> 5, lane = tid & 31;
    const int g = lane >> 2, t4 = lane & 3;
    const int wm = (wid & 1) * 64, wn = (wid >> 1) * 32;
    const int n0 = blockIdx.x * 128, m0 = blockIdx.y * 128, z = blockIdx.z;

    GemmAcc C = {};
    gemm128_mainloop(g_xhi + (size_t)m0 * Ee, g_xlo + (size_t)m0 * Ee,
                     g_wThi + ((size_t)z * Ee + n0) * Ee,
                     g_wTlo + ((size_t)z * Ee + n0) * Ee, sm, C);

    const float qs = (z == 0) ? 0.125f : 1.0f;
    __nv_bfloat16* Oh = (z == 0) ? g_Qhi : (z == 1) ? g_Khi : g_Vhi;
    __nv_bfloat16* Ol = (z == 0) ? g_Qlo : (z == 1) ? g_Klo : g_Vlo;

#pragma unroll
    for (int mf = 0; mf < 4; mf++)
#pragma unroll
        for (int nf = 0; nf < 4; nf++) {
            int col = n0 + wn + nf * 8 + t4 * 2;
            int h = col >> 6, d = col & 63;
#pragma unroll
            for (int half = 0; half < 2; half++) {
                int row = m0 + wm + mf * 16 + g + half * 8;
                int b = row >> 11, s = row & (Ss - 1);
                size_t di = (((size_t)(b * Hh + h)) * Ss + s) * Dd + d;
                __nv_bfloat16 h0, l0, h1, l1;
                split2(C.a[mf][nf][half * 2] * qs, h0, l0);
                split2(C.a[mf][nf][half * 2 + 1] * qs, h1, l1);
                *(__nv_bfloat162*)&Oh[di] = __nv_bfloat162(h0, h1);
                *(__nv_bfloat162*)&Ol[di] = __nv_bfloat162(l0, l1);
            }
        }
}

__global__ __launch_bounds__(256) void gemm_proj(const float* __restrict__ bo,
                                                 float* __restrict__ out) {
    __shared__ __nv_bfloat16 sm[20480];
    const int tid = threadIdx.x;
    const int wid = tid >> 5, lane = tid & 31;
    const int g = lane >> 2, t4 = lane & 3;
    const int wm = (wid & 1) * 64, wn = (wid >> 1) * 32;
    const int n0 = blockIdx.x * 128, m0 = blockIdx.y * 128;

    GemmAcc C = {};
    gemm128_mainloop(g_Ohi + (size_t)m0 * Ee, g_Olo + (size_t)m0 * Ee,
                     g_wThi + ((size_t)3 * Ee + n0) * Ee,
                     g_wTlo + ((size_t)3 * Ee + n0) * Ee, sm, C);

#pragma unroll
    for (int mf = 0; mf < 4; mf++)
#pragma unroll
        for (int nf = 0; nf < 4; nf++) {
            int col = n0 + wn + nf * 8 + t4 * 2;
            float2 bias = *(const float2*)&bo[col];
#pragma unroll
            for (int half = 0; half < 2; half++) {
                int row = m0 + wm + mf * 16 + g + half * 8;
                *(float2*)&out[(size_t)row * Ee + col] =
                    make_float2(C.a[mf][nf][half * 2] + bias.x,
                                C.a[mf][nf][half * 2 + 1] + bias.y);
            }
        }
}

// ===========================================================================
// Attention: compensated-bf16 mma flash attention, 8 warps x 16 q-rows.
// Q fragments register-resident; Q smem region reused for P.
// Pitch 72 bf16 (36 words): ldmatrix conflict-free.
// ===========================================================================
#define AP2 72
#define A_PH 0
#define A_PL 9216
#define A_KH 18432
#define A_KL 23040
#define A_VH 27648
#define A_VL 32256
#define ATTN_SMEM (36864 * 2)

__global__ __launch_bounds__(256) void attn_bf16() {
    extern __shared__ __nv_bfloat16 sm[];
    const int tid = threadIdx.x;
    const int wid = tid >> 5, lane = tid & 31;
    const int g = lane >> 2, t4 = lane & 3;
    const int grp = lane >> 3, rr = lane & 7;
    const int bh = blockIdx.y;
    const int qb = gridDim.x - 1 - blockIdx.x;   // heavy tiles first
    const int q0 = qb * 128;
    const int wrow = wid * 16;

    const __nv_bfloat16* Qh_g = g_Qhi + (size_t)bh * Ss * Dd;
    const __nv_bfloat16* Ql_g = g_Qlo + (size_t)bh * Ss * Dd;
    const __nv_bfloat16* Kh_g = g_Khi + (size_t)bh * Ss * Dd;
    const __nv_bfloat16* Kl_g = g_Klo + (size_t)bh * Ss * Dd;
    const __nv_bfloat16* Vh_g = g_Vthi + (size_t)bh * Dd * Ss;
    const __nv_bfloat16* Vl_g = g_Vtlo + (size_t)bh * Dd * Ss;

    // stage Q hi/lo into (future) P region
#pragma unroll
    for (int t = 0; t < 8; t++) {
        int slot = t * 256 + tid;
        int tile = slot >> 10, s2 = slot & 1023;
        int r = s2 >> 3, c = (s2 & 7) * 8;
        *(uint4*)(sm + (tile ? A_PL : A_PH) + r * AP2 + c) =
            *(const uint4*)((tile ? Ql_g : Qh_g) + (size_t)(q0 + r) * Dd + c);
    }
    __syncthreads();

    // hoist Q fragments to registers (A-frag lane mapping)
    const int qoff = (wrow + (grp & 1) * 8 + rr) * AP2 + (grp >> 1) * 8;
    uint32_t qh[4][4], ql[4][4];
#pragma unroll
    for (int ks = 0; ks < 4; ks++) {
        ldsm4(qh[ks], lds_addr(sm + A_PH + qoff + ks * 16));
        ldsm4(ql[ks], lds_addr(sm + A_PL + qoff + ks * 16));
    }

    const int boff = rr * AP2 + grp * 8;   // B-frag base (nf adds 8*AP2 rows)

    float m_i[2] = {-1e30f, -1e30f}, l_i[2] = {0.f, 0.f};
    float o[8][4] = {};

    const int ktmax = 2 * qb + 2;
    for (int kt = 0; kt < ktmax; kt++) {
        const int k0 = kt * 64;
        __syncthreads();    // prior PV smem reads done (+ Q frag loads, iter 0)
#pragma unroll
        for (int t = 0; t < 8; t++) {
            int slot = t * 256 + tid;
            int tensor = slot >> 9, s2 = slot & 511;
            int r = s2 >> 3, c = (s2 & 7) * 8;
            const __nv_bfloat16* src =
                (tensor == 0) ? Kh_g + (size_t)(k0 + r) * Dd + c :
                (tensor == 1) ? Kl_g + (size_t)(k0 + r) * Dd + c :
                (tensor == 2) ? Vh_g + (size_t)r * Ss + k0 + c :
                                Vl_g + (size_t)r * Ss + k0 + c;
            int dst = (tensor == 0) ? A_KH : (tensor == 1) ? A_KL :
                      (tensor == 2) ? A_VH : A_VL;
            *(uint4*)(sm + dst + r * AP2 + c) = *(const uint4*)src;
        }
        __syncthreads();

        // ---- S = Q K^T ----
        float sc[8][4] = {};
#pragma unroll
        for (int nf = 0; nf < 8; nf++) {
            uint32_t kh8[8], kl8[8];
            ldsm4(kh8,     lds_addr(sm + A_KH + boff + nf * 8 * AP2));
            ldsm4(kh8 + 4, lds_addr(sm + A_KH + boff + nf * 8 * AP2 + 32));
            ldsm4(kl8,     lds_addr(sm + A_KL + boff + nf * 8 * AP2));
            ldsm4(kl8 + 4, lds_addr(sm + A_KL + boff + nf * 8 * AP2 + 32));
#pragma unroll
            for (int ks = 0; ks < 4; ks++) {
                mma_bf16(sc[nf], qh[ks], kh8[ks * 2], kh8[ks * 2 + 1]);
                mma_bf16(sc[nf], qh[ks], kl8[ks * 2], kl8[ks * 2 + 1]);
                mma_bf16(sc[nf], ql[ks], kh8[ks * 2], kh8[ks * 2 + 1]);
            }
        }

        // ---- causal mask ----
        if (kt >= 2 * qb) {
#pragma unroll
            for (int nf = 0; nf < 8; nf++)
#pragma unroll
                for (int j = 0; j < 4; j++) {
                    int col = k0 + nf * 8 + t4 * 2 + (j & 1);
                    int row = q0 + wrow + g + (j >> 1) * 8;
                    if (col > row) sc[nf][j] = -1e30f;
                }
        }

        // ---- online softmax ----
#pragma unroll
        for (int half = 0; half < 2; half++) {
            const int j0 = half * 2;
            float mrow = -1e30f;
#pragma unroll
            for (int nf = 0; nf < 8; nf++)
                mrow = fmaxf(mrow, fmaxf(sc[nf][j0], sc[nf][j0 + 1]));
            mrow = fmaxf(mrow, __shfl_xor_sync(0xffffffffu, mrow, 1));
            mrow = fmaxf(mrow, __shfl_xor_sync(0xffffffffu, mrow, 2));
            float mnew = fmaxf(m_i[half], mrow);
            float corr = __expf(m_i[half] - mnew);
            m_i[half] = mnew;
            float ps = 0.f;
#pragma unroll
            for (int nf = 0; nf < 8; nf++) {
                float e0 = __expf(sc[nf][j0] - mnew);
                float e1 = __expf(sc[nf][j0 + 1] - mnew);
                sc[nf][j0] = e0; sc[nf][j0 + 1] = e1;
                ps += e0 + e1;
            }
            ps += __shfl_xor_sync(0xffffffffu, ps, 1);
            ps += __shfl_xor_sync(0xffffffffu, ps, 2);
            l_i[half] = l_i[half] * corr + ps;
#pragma unroll
            for (int nf = 0; nf < 8; nf++) {
                o[nf][j0] *= corr;
                o[nf][j0 + 1] *= corr;
            }
        }

        // ---- P -> smem (warp-private rows) ----
#pragma unroll
        for (int nf = 0; nf < 8; nf++) {
            int col = nf * 8 + t4 * 2;
            __nv_bfloat16 h0, l0, h1, l1;
            split2(sc[nf][0], h0, l0);
            split2(sc[nf][1], h1, l1);
            *(__nv_bfloat162*)(sm + A_PH + (wrow + g) * AP2 + col) = __nv_bfloat162(h0, h1);
            *(__nv_bfloat162*)(sm + A_PL + (wrow + g) * AP2 + col) = __nv_bfloat162(l0, l1);
            split2(sc[nf][2], h0, l0);
            split2(sc[nf][3], h1, l1);
            *(__nv_bfloat162*)(sm + A_PH + (wrow + g + 8) * AP2 + col) = __nv_bfloat162(h0, h1);
            *(__nv_bfloat162*)(sm + A_PL + (wrow + g + 8) * AP2 + col) = __nv_bfloat162(l0, l1);
        }
        __syncwarp();

        // ---- O += P V ----
        uint32_t ph[4][4], pl[4][4];
#pragma unroll
        for (int ks = 0; ks < 4; ks++) {
            ldsm4(ph[ks], lds_addr(sm + A_PH + qoff + ks * 16));
            ldsm4(pl[ks], lds_addr(sm + A_PL + qoff + ks * 16));
        }
#pragma unroll
        for (int nf = 0; nf < 8; nf++) {
            uint32_t vh8[8], vl8[8];
            ldsm4(vh8,     lds_addr(sm + A_VH + boff + nf * 8 * AP2));
            ldsm4(vh8 + 4, lds_addr(sm + A_VH + boff + nf * 8 * AP2 + 32));
            ldsm4(vl8,     lds_addr(sm + A_VL + boff + nf * 8 * AP2));
            ldsm4(vl8 + 4, lds_addr(sm + A_VL + boff + nf * 8 * AP2 + 32));
#pragma unroll
            for (int ks = 0; ks < 4; ks++) {
                mma_bf16(o[nf], ph[ks], vh8[ks * 2], vh8[ks * 2 + 1]);
                mma_bf16(o[nf], ph[ks], vl8[ks * 2], vl8[ks * 2 + 1]);
                mma_bf16(o[nf], pl[ks], vh8[ks * 2], vh8[ks * 2 + 1]);
            }
        }
    }

    // ---- epilogue ----
    const int b = bh >> 4, h = bh & 15;
    float inv_lo = 1.0f / l_i[0];
    float inv_hi = 1.0f / l_i[1];
#pragma unroll
    for (int nf = 0; nf < 8; nf++) {
        int srow = q0 + wrow + g;
        int col = h * 64 + nf * 8 + t4 * 2;
        size_t r0i = ((size_t)b * Ss + srow) * Ee + col;
        size_t r1i = ((size_t)b * Ss + srow + 8) * Ee + col;
        __nv_bfloat16 h0, l0, h1, l1;
        split2(o[nf][0] * inv_lo, h0, l0);
        split2(o[nf][1] * inv_lo, h1, l1);
        *(__nv_bfloat162*)&g_Ohi[r0i] = __nv_bfloat162(h0, h1);
        *(__nv_bfloat162*)&g_Olo[r0i] = __nv_bfloat162(l0, l1);
        split2(o[nf][2] * inv_hi, h0, l0);
        split2(o[nf][3] * inv_hi, h1, l1);
        *(__nv_bfloat162*)&g_Ohi[r1i] = __nv_bfloat162(h0, h1);
        *(__nv_bfloat162*)&g_Olo[r1i] = __nv_bfloat162(l0, l1);
    }
}

// ---------------------------------------------------------------------------
extern "C" void kernel_launch(void* const* d_in, const int* in_sizes, int n_in,
                              void* d_out, int out_size)
{
    const float* x  = (const float*)d_in[0];
    const float* Wq = (const float*)d_in[1];
    const float* Wk = (const float*)d_in[2];
    const float* Wv = (const float*)d_in[3];
    const float* Wo = (const float*)d_in[4];
    const float* bo = (const float*)d_in[5];
    float* out = (float*)d_out;

    cudaFuncSetAttribute(attn_bf16, cudaFuncAttributeMaxDynamicSharedMemorySize, ATTN_SMEM);

    split_x<<<16384, 256>>>(x);
    wsplit<<<dim3(32, 32, 4), dim3(32, 8)>>>(Wq, Wk, Wv, Wo);
    gemm_qkv<<<dim3(8, 32, 3), 256>>>();
    vtrans<<<dim3(64, 2, 64), dim3(32, 8)>>>();
    attn_bf16<<<dim3(16, 32), 256, ATTN_SMEM>>>();
    gemm_proj<<<dim3(8, 32), 256>>>(bo, out);
}

// round 8
// speedup vs baseline: 3.3741x; 1.5292x over previous
#include <cuda_runtime.h>
#include <cuda_fp16.h>
#include <cstdint>

#define Ss 2048
#define Ee 1024
#define Hh 16
#define Dd 64

// ---------------- device scratch ------------------------------------------
__device__ __half g_xhi[(size_t)4096 * 1024];
__device__ __half g_xlo[(size_t)4096 * 1024];
__device__ __half g_wThi[(size_t)4 * 1024 * 1024];   // [mat][n][k], hi only
__device__ __half g_Qhi[(size_t)32 * Ss * Dd];       // [bh][s][d], pre-scaled
__device__ __half g_Qlo[(size_t)32 * Ss * Dd];
__device__ __half g_Khi[(size_t)32 * Ss * Dd];       // hi only
__device__ __half g_Vhi[(size_t)32 * Ss * Dd];       // hi only
__device__ __half g_Vthi[(size_t)32 * Dd * Ss];      // [bh][d][s], hi only
__device__ __half g_Ohi[(size_t)4096 * 1024];        // [b*S+s][h*64+d]
__device__ __half g_Olo[(size_t)4096 * 1024];

// ---------------- helpers --------------------------------------------------
__device__ __forceinline__ void mma_f16(float c[4],
                                        const uint32_t a[4],
                                        uint32_t b0, uint32_t b1) {
    asm volatile(
        "mma.sync.aligned.m16n8k16.row.col.f32.f16.f16.f32 "
        "{%0,%1,%2,%3},{%4,%5,%6,%7},{%8,%9},{%0,%1,%2,%3};"
        : "+f"(c[0]), "+f"(c[1]), "+f"(c[2]), "+f"(c[3])
        : "r"(a[0]), "r"(a[1]), "r"(a[2]), "r"(a[3]), "r"(b0), "r"(b1));
}
__device__ __forceinline__ uint32_t lds_addr(const void* p) {
    return (uint32_t)__cvta_generic_to_shared(p);
}
__device__ __forceinline__ void ldsm4(uint32_t r[4], uint32_t a) {
    asm volatile("ldmatrix.sync.aligned.m8n8.x4.shared.b16 {%0,%1,%2,%3}, [%4];"
        : "=r"(r[0]), "=r"(r[1]), "=r"(r[2]), "=r"(r[3]) : "r"(a));
}
__device__ __forceinline__ void split2(float v, __half& h, __half& l) {
    h = __float2half(v);
    l = __float2half(v - __half2float(h));
}

// ===========================================================================
// Pre-passes
// ===========================================================================
__global__ __launch_bounds__(256) void split_x(const float* __restrict__ src) {
    int i = blockIdx.x * 256 + threadIdx.x;
    float v = src[i];
    __half h, l;
    split2(v, h, l);
    g_xhi[i] = h;
    g_xlo[i] = l;
}

// transpose + round weights: g_wThi[z][n][k] = fp16(W_z[k][n])
__global__ __launch_bounds__(256) void wsplit(
    const float* __restrict__ Wq, const float* __restrict__ Wk,
    const float* __restrict__ Wv, const float* __restrict__ Wo)
{
    __shared__ float t[32][33];
    const int z = blockIdx.z;
    const float* W = (z == 0) ? Wq : (z == 1) ? Wk : (z == 2) ? Wv : Wo;
    const int tx = threadIdx.x, ty = threadIdx.y;
    const int bx = blockIdx.x, by = blockIdx.y;
#pragma unroll
    for (int i = 0; i < 32; i += 8)
        t[ty + i][tx] = W[(size_t)(by * 32 + ty + i) * Ee + bx * 32 + tx];
    __syncthreads();
    const size_t base = (size_t)z * Ee * Ee;
#pragma unroll
    for (int i = 0; i < 32; i += 8) {
        int n = bx * 32 + ty + i, k = by * 32 + tx;
        g_wThi[base + (size_t)n * Ee + k] = __float2half(t[tx][ty + i]);
    }
}

// V transpose per head (hi only): g_Vthi[bh][d][s] = g_Vhi[bh][s][d]
__global__ __launch_bounds__(256) void vtrans() {
    __shared__ __half t[32][33];
    const int bh = blockIdx.z;
    const __half* src = g_Vhi + (size_t)bh * Ss * Dd;
    __half* dst = g_Vthi + (size_t)bh * Dd * Ss;
    const int tx = threadIdx.x, ty = threadIdx.y;
    const int s0 = blockIdx.x * 32, d0 = blockIdx.y * 32;
#pragma unroll
    for (int i = 0; i < 32; i += 8)
        t[ty + i][tx] = src[(size_t)(s0 + ty + i) * Dd + d0 + tx];
    __syncthreads();
#pragma unroll
    for (int i = 0; i < 32; i += 8)
        dst[(size_t)(d0 + ty + i) * Ss + s0 + tx] = t[tx][ty + i];
}

// ===========================================================================
// 2-term fp16 GEMM (QKV / proj): C = Ah*B + Al*B.
// 256 thr, tile 128x128, 32 K-chunks of 32. Pitch 40 halfs (conflict-free).
// ===========================================================================
#define GP 40
#define G_AH 0
#define G_AL 5120
#define G_BH 10240

struct GemmAcc { float a[4][4][4]; };

__device__ __forceinline__ void gemm128_mainloop(
    const __half* __restrict__ Ah_g, const __half* __restrict__ Al_g,
    const __half* __restrict__ Bh_g,
    __half* sm, GemmAcc& C)
{
    const int tid = threadIdx.x;
    const int wid = tid >> 5, lane = tid & 31;
    const int grp = lane >> 3, rr = lane & 7;
    const int wm = (wid & 1) * 64, wn = (wid >> 1) * 32;
    const int r0 = tid >> 2, c0 = (tid & 3) * 8;

    uint4 rAh[2], rAl[2], rBh[2];
#pragma unroll
    for (int j = 0; j < 2; j++) {
        size_t go = (size_t)(r0 + j * 64) * Ee + c0;
        rAh[j] = *(const uint4*)(Ah_g + go);
        rAl[j] = *(const uint4*)(Al_g + go);
        rBh[j] = *(const uint4*)(Bh_g + go);
    }

    const int aoff = (wm + (grp & 1) * 8 + rr) * GP + (grp >> 1) * 8;
    const int boff = (wn + rr) * GP + grp * 8;

    for (int kc = 0; kc < 32; kc++) {
#pragma unroll
        for (int j = 0; j < 2; j++) {
            int si = (r0 + j * 64) * GP + c0;
            *(uint4*)(sm + G_AH + si) = rAh[j];
            *(uint4*)(sm + G_AL + si) = rAl[j];
            *(uint4*)(sm + G_BH + si) = rBh[j];
        }
        __syncthreads();

        if (kc < 31) {
            int k0n = (kc + 1) * 32;
#pragma unroll
            for (int j = 0; j < 2; j++) {
                size_t go = (size_t)(r0 + j * 64) * Ee + k0n + c0;
                rAh[j] = *(const uint4*)(Ah_g + go);
                rAl[j] = *(const uint4*)(Al_g + go);
                rBh[j] = *(const uint4*)(Bh_g + go);
            }
        }

        uint32_t bhf[4][4];
#pragma unroll
        for (int nf = 0; nf < 4; nf++)
            ldsm4(bhf[nf], lds_addr(sm + G_BH + boff + nf * 8 * GP));
#pragma unroll
        for (int ks = 0; ks < 2; ks++) {
            uint32_t ahf[4][4], alf[4][4];
#pragma unroll
            for (int mf = 0; mf < 4; mf++) {
                ldsm4(ahf[mf], lds_addr(sm + G_AH + aoff + mf * 16 * GP + ks * 16));
                ldsm4(alf[mf], lds_addr(sm + G_AL + aoff + mf * 16 * GP + ks * 16));
            }
#pragma unroll
            for (int nf = 0; nf < 4; nf++) {
                uint32_t b0 = bhf[nf][ks * 2], b1 = bhf[nf][ks * 2 + 1];
#pragma unroll
                for (int mf = 0; mf < 4; mf++) {
                    mma_f16(C.a[mf][nf], ahf[mf], b0, b1);
                    mma_f16(C.a[mf][nf], alf[mf], b0, b1);
                }
            }
        }
        __syncthreads();
    }
}

__global__ __launch_bounds__(256) void gemm_qkv() {
    __shared__ __half sm[15360];
    const int tid = threadIdx.x;
    const int wid = tid >> 5, lane = tid & 31;
    const int g = lane >> 2, t4 = lane & 3;
    const int wm = (wid & 1) * 64, wn = (wid >> 1) * 32;
    const int n0 = blockIdx.x * 128, m0 = blockIdx.y * 128, z = blockIdx.z;

    GemmAcc C = {};
    gemm128_mainloop(g_xhi + (size_t)m0 * Ee, g_xlo + (size_t)m0 * Ee,
                     g_wThi + ((size_t)z * Ee + n0) * Ee, sm, C);

    const float qs = (z == 0) ? 0.125f : 1.0f;
    __half* Oh = (z == 0) ? g_Qhi : (z == 1) ? g_Khi : g_Vhi;

#pragma unroll
    for (int mf = 0; mf < 4; mf++)
#pragma unroll
        for (int nf = 0; nf < 4; nf++) {
            int col = n0 + wn + nf * 8 + t4 * 2;
            int h = col >> 6, d = col & 63;
#pragma unroll
            for (int half2i = 0; half2i < 2; half2i++) {
                int row = m0 + wm + mf * 16 + g + half2i * 8;
                int b = row >> 11, s = row & (Ss - 1);
                size_t di = (((size_t)(b * Hh + h)) * Ss + s) * Dd + d;
                float v0 = C.a[mf][nf][half2i * 2] * qs;
                float v1 = C.a[mf][nf][half2i * 2 + 1] * qs;
                if (z == 0) {
                    __half h0, l0, h1, l1;
                    split2(v0, h0, l0);
                    split2(v1, h1, l1);
                    *(__half2*)&g_Qhi[di] = __half2(h0, h1);
                    *(__half2*)&g_Qlo[di] = __half2(l0, l1);
                } else {
                    *(__half2*)&Oh[di] = __half2(__float2half(v0), __float2half(v1));
                }
            }
        }
}

__global__ __launch_bounds__(256) void gemm_proj(const float* __restrict__ bo,
                                                 float* __restrict__ out) {
    __shared__ __half sm[15360];
    const int tid = threadIdx.x;
    const int wid = tid >> 5, lane = tid & 31;
    const int g = lane >> 2, t4 = lane & 3;
    const int wm = (wid & 1) * 64, wn = (wid >> 1) * 32;
    const int n0 = blockIdx.x * 128, m0 = blockIdx.y * 128;

    GemmAcc C = {};
    gemm128_mainloop(g_Ohi + (size_t)m0 * Ee, g_Olo + (size_t)m0 * Ee,
                     g_wThi + ((size_t)3 * Ee + n0) * Ee, sm, C);

#pragma unroll
    for (int mf = 0; mf < 4; mf++)
#pragma unroll
        for (int nf = 0; nf < 4; nf++) {
            int col = n0 + wn + nf * 8 + t4 * 2;
            float2 bias = *(const float2*)&bo[col];
#pragma unroll
            for (int half2i = 0; half2i < 2; half2i++) {
                int row = m0 + wm + mf * 16 + g + half2i * 8;
                *(float2*)&out[(size_t)row * Ee + col] =
                    make_float2(C.a[mf][nf][half2i * 2] + bias.x,
                                C.a[mf][nf][half2i * 2 + 1] + bias.y);
            }
        }
}

// ===========================================================================
// Attention: 2-term fp16 flash attention, 8 warps x 16 q-rows.
// Q hi/lo register-resident; Q smem reused for P hi/lo; K,V hi only.
// Pitch 72 halfs (conflict-free ldmatrix).
// ===========================================================================
#define AP2 72
#define A_PH 0
#define A_PL 9216
#define A_KH 18432
#define A_VH 23040
#define ATTN_SMEM (27648 * 2)

__global__ __launch_bounds__(256) void attn_f16() {
    extern __shared__ __half sm[];
    const int tid = threadIdx.x;
    const int wid = tid >> 5, lane = tid & 31;
    const int g = lane >> 2, t4 = lane & 3;
    const int grp = lane >> 3, rr = lane & 7;
    const int bh = blockIdx.y;
    const int qb = gridDim.x - 1 - blockIdx.x;   // heavy tiles first
    const int q0 = qb * 128;
    const int wrow = wid * 16;

    const __half* Qh_g = g_Qhi + (size_t)bh * Ss * Dd;
    const __half* Ql_g = g_Qlo + (size_t)bh * Ss * Dd;
    const __half* Kh_g = g_Khi + (size_t)bh * Ss * Dd;
    const __half* Vh_g = g_Vthi + (size_t)bh * Dd * Ss;

    // stage Q hi/lo into (future) P region
#pragma unroll
    for (int t = 0; t < 8; t++) {
        int slot = t * 256 + tid;
        int tile = slot >> 10, s2 = slot & 1023;
        int r = s2 >> 3, c = (s2 & 7) * 8;
        *(uint4*)(sm + (tile ? A_PL : A_PH) + r * AP2 + c) =
            *(const uint4*)((tile ? Ql_g : Qh_g) + (size_t)(q0 + r) * Dd + c);
    }
    __syncthreads();

    const int qoff = (wrow + (grp & 1) * 8 + rr) * AP2 + (grp >> 1) * 8;
    uint32_t qh[4][4], ql[4][4];
#pragma unroll
    for (int ks = 0; ks < 4; ks++) {
        ldsm4(qh[ks], lds_addr(sm + A_PH + qoff + ks * 16));
        ldsm4(ql[ks], lds_addr(sm + A_PL + qoff + ks * 16));
    }

    const int boff = rr * AP2 + grp * 8;

    float m_i[2] = {-1e30f, -1e30f}, l_i[2] = {0.f, 0.f};
    float o[8][4] = {};

    const int ktmax = 2 * qb + 2;
    for (int kt = 0; kt < ktmax; kt++) {
        const int k0 = kt * 64;
        __syncthreads();
#pragma unroll
        for (int t = 0; t < 4; t++) {
            int slot = t * 256 + tid;
            int tensor = slot >> 9, s2 = slot & 511;
            int r = s2 >> 3, c = (s2 & 7) * 8;
            const __half* src = tensor ? Vh_g + (size_t)r * Ss + k0 + c
                                       : Kh_g + (size_t)(k0 + r) * Dd + c;
            *(uint4*)(sm + (tensor ? A_VH : A_KH) + r * AP2 + c) = *(const uint4*)src;
        }
        __syncthreads();

        // ---- S = Q K^T ----
        float sc[8][4] = {};
#pragma unroll
        for (int nf = 0; nf < 8; nf++) {
            uint32_t k8[8];
            ldsm4(k8,     lds_addr(sm + A_KH + boff + nf * 8 * AP2));
            ldsm4(k8 + 4, lds_addr(sm + A_KH + boff + nf * 8 * AP2 + 32));
#pragma unroll
            for (int ks = 0; ks < 4; ks++) {
                mma_f16(sc[nf], qh[ks], k8[ks * 2], k8[ks * 2 + 1]);
                mma_f16(sc[nf], ql[ks], k8[ks * 2], k8[ks * 2 + 1]);
            }
        }

        // ---- causal mask ----
        if (kt >= 2 * qb) {
#pragma unroll
            for (int nf = 0; nf < 8; nf++)
#pragma unroll
                for (int j = 0; j < 4; j++) {
                    int col = k0 + nf * 8 + t4 * 2 + (j & 1);
                    int row = q0 + wrow + g + (j >> 1) * 8;
                    if (col > row) sc[nf][j] = -1e30f;
                }
        }

        // ---- online softmax ----
#pragma unroll
        for (int half2i = 0; half2i < 2; half2i++) {
            const int j0 = half2i * 2;
            float mrow = -1e30f;
#pragma unroll
            for (int nf = 0; nf < 8; nf++)
                mrow = fmaxf(mrow, fmaxf(sc[nf][j0], sc[nf][j0 + 1]));
            mrow = fmaxf(mrow, __shfl_xor_sync(0xffffffffu, mrow, 1));
            mrow = fmaxf(mrow, __shfl_xor_sync(0xffffffffu, mrow, 2));
            float mnew = fmaxf(m_i[half2i], mrow);
            float corr = __expf(m_i[half2i] - mnew);
            m_i[half2i] = mnew;
            float ps = 0.f;
#pragma unroll
            for (int nf = 0; nf < 8; nf++) {
                float e0 = __expf(sc[nf][j0] - mnew);
                float e1 = __expf(sc[nf][j0 + 1] - mnew);
                sc[nf][j0] = e0; sc[nf][j0 + 1] = e1;
                ps += e0 + e1;
            }
            ps += __shfl_xor_sync(0xffffffffu, ps, 1);
            ps += __shfl_xor_sync(0xffffffffu, ps, 2);
            l_i[half2i] = l_i[half2i] * corr + ps;
#pragma unroll
            for (int nf = 0; nf < 8; nf++) {
                o[nf][j0] *= corr;
                o[nf][j0 + 1] *= corr;
            }
        }

        // ---- P -> smem hi/lo (warp-private rows) ----
#pragma unroll
        for (int nf = 0; nf < 8; nf++) {
            int col = nf * 8 + t4 * 2;
            __half h0, l0, h1, l1;
            split2(sc[nf][0], h0, l0);
            split2(sc[nf][1], h1, l1);
            *(__half2*)(sm + A_PH + (wrow + g) * AP2 + col) = __half2(h0, h1);
            *(__half2*)(sm + A_PL + (wrow + g) * AP2 + col) = __half2(l0, l1);
            split2(sc[nf][2], h0, l0);
            split2(sc[nf][3], h1, l1);
            *(__half2*)(sm + A_PH + (wrow + g + 8) * AP2 + col) = __half2(h0, h1);
            *(__half2*)(sm + A_PL + (wrow + g + 8) * AP2 + col) = __half2(l0, l1);
        }
        __syncwarp();

        // ---- O += P V ----
        uint32_t ph[4][4], pl[4][4];
#pragma unroll
        for (int ks = 0; ks < 4; ks++) {
            ldsm4(ph[ks], lds_addr(sm + A_PH + qoff + ks * 16));
            ldsm4(pl[ks], lds_addr(sm + A_PL + qoff + ks * 16));
        }
#pragma unroll
        for (int nf = 0; nf < 8; nf++) {
            uint32_t v8[8];
            ldsm4(v8,     lds_addr(sm + A_VH + boff + nf * 8 * AP2));
            ldsm4(v8 + 4, lds_addr(sm + A_VH + boff + nf * 8 * AP2 + 32));
#pragma unroll
            for (int ks = 0; ks < 4; ks++) {
                mma_f16(o[nf], ph[ks], v8[ks * 2], v8[ks * 2 + 1]);
                mma_f16(o[nf], pl[ks], v8[ks * 2], v8[ks * 2 + 1]);
            }
        }
    }

    // ---- epilogue: O/l -> hi/lo fp16, proj layout [b*S+s][h*64+d] ----
    const int b = bh >> 4, h = bh & 15;
    float inv_lo = 1.0f / l_i[0];
    float inv_hi = 1.0f / l_i[1];
#pragma unroll
    for (int nf = 0; nf < 8; nf++) {
        int srow = q0 + wrow + g;
        int col = h * 64 + nf * 8 + t4 * 2;
        size_t r0i = ((size_t)b * Ss + srow) * Ee + col;
        size_t r1i = ((size_t)b * Ss + srow + 8) * Ee + col;
        __half h0, l0, h1, l1;
        split2(o[nf][0] * inv_lo, h0, l0);
        split2(o[nf][1] * inv_lo, h1, l1);
        *(__half2*)&g_Ohi[r0i] = __half2(h0, h1);
        *(__half2*)&g_Olo[r0i] = __half2(l0, l1);
        split2(o[nf][2] * inv_hi, h0, l0);
        split2(o[nf][3] * inv_hi, h1, l1);
        *(__half2*)&g_Ohi[r1i] = __half2(h0, h1);
        *(__half2*)&g_Olo[r1i] = __half2(l0, l1);
    }
}

// ---------------------------------------------------------------------------
extern "C" void kernel_launch(void* const* d_in, const int* in_sizes, int n_in,
                              void* d_out, int out_size)
{
    const float* x  = (const float*)d_in[0];
    const float* Wq = (const float*)d_in[1];
    const float* Wk = (const float*)d_in[2];
    const float* Wv = (const float*)d_in[3];
    const float* Wo = (const float*)d_in[4];
    const float* bo = (const float*)d_in[5];
    float* out = (float*)d_out;

    cudaFuncSetAttribute(attn_f16, cudaFuncAttributeMaxDynamicSharedMemorySize, ATTN_SMEM);

    split_x<<<16384, 256>>>(x);
    wsplit<<<dim3(32, 32, 4), dim3(32, 8)>>>(Wq, Wk, Wv, Wo);
    gemm_qkv<<<dim3(8, 32, 3), 256>>>();
    vtrans<<<dim3(64, 2, 32), dim3(32, 8)>>>();
    attn_f16<<<dim3(16, 32), 256, ATTN_SMEM>>>();
    gemm_proj<<<dim3(8, 32), 256>>>(bo, out);
}

// round 9
// speedup vs baseline: 4.8539x; 1.4386x over previous
#include <cuda_runtime.h>
#include <cuda_fp16.h>
#include <cstdint>

#define Ss 2048
#define Ee 1024
#define Hh 16
#define Dd 64

// ---------------- device scratch ------------------------------------------
__device__ __half g_xh[(size_t)4096 * 1024];
__device__ __half g_wT[(size_t)4 * 1024 * 1024];    // [mat][n][k]
__device__ __half g_Qh[(size_t)32 * Ss * Dd];       // [bh][s][d], pre-scaled
__device__ __half g_Kh[(size_t)32 * Ss * Dd];
__device__ __half g_Vh[(size_t)32 * Ss * Dd];
__device__ __half g_Vt[(size_t)32 * Dd * Ss];       // [bh][d][s]
__device__ __half g_Oh[(size_t)4096 * 1024];        // [b*S+s][h*64+d]

// ---------------- helpers --------------------------------------------------
__device__ __forceinline__ void mma_f16(float c[4],
                                        const uint32_t a[4],
                                        uint32_t b0, uint32_t b1) {
    asm volatile(
        "mma.sync.aligned.m16n8k16.row.col.f32.f16.f16.f32 "
        "{%0,%1,%2,%3},{%4,%5,%6,%7},{%8,%9},{%0,%1,%2,%3};"
        : "+f"(c[0]), "+f"(c[1]), "+f"(c[2]), "+f"(c[3])
        : "r"(a[0]), "r"(a[1]), "r"(a[2]), "r"(a[3]), "r"(b0), "r"(b1));
}
__device__ __forceinline__ uint32_t lds_addr(const void* p) {
    return (uint32_t)__cvta_generic_to_shared(p);
}
__device__ __forceinline__ void ldsm4(uint32_t r[4], uint32_t a) {
    asm volatile("ldmatrix.sync.aligned.m8n8.x4.shared.b16 {%0,%1,%2,%3}, [%4];"
        : "=r"(r[0]), "=r"(r[1]), "=r"(r[2]), "=r"(r[3]) : "r"(a));
}

// ===========================================================================
// Pre-passes
// ===========================================================================
__global__ __launch_bounds__(256) void round_x(const float* __restrict__ src) {
    int i = blockIdx.x * 256 + threadIdx.x;
    g_xh[i] = __float2half(src[i]);
}

// transpose + round weights: g_wT[z][n][k] = fp16(W_z[k][n])
__global__ __launch_bounds__(256) void wsplit(
    const float* __restrict__ Wq, const float* __restrict__ Wk,
    const float* __restrict__ Wv, const float* __restrict__ Wo)
{
    __shared__ float t[32][33];
    const int z = blockIdx.z;
    const float* W = (z == 0) ? Wq : (z == 1) ? Wk : (z == 2) ? Wv : Wo;
    const int tx = threadIdx.x, ty = threadIdx.y;
    const int bx = blockIdx.x, by = blockIdx.y;
#pragma unroll
    for (int i = 0; i < 32; i += 8)
        t[ty + i][tx] = W[(size_t)(by * 32 + ty + i) * Ee + bx * 32 + tx];
    __syncthreads();
    const size_t base = (size_t)z * Ee * Ee;
#pragma unroll
    for (int i = 0; i < 32; i += 8) {
        int n = bx * 32 + ty + i, k = by * 32 + tx;
        g_wT[base + (size_t)n * Ee + k] = __float2half(t[tx][ty + i]);
    }
}

// V transpose per head: g_Vt[bh][d][s] = g_Vh[bh][s][d]
__global__ __launch_bounds__(256) void vtrans() {
    __shared__ __half t[32][33];
    const int bh = blockIdx.z;
    const __half* src = g_Vh + (size_t)bh * Ss * Dd;
    __half* dst = g_Vt + (size_t)bh * Dd * Ss;
    const int tx = threadIdx.x, ty = threadIdx.y;
    const int s0 = blockIdx.x * 32, d0 = blockIdx.y * 32;
#pragma unroll
    for (int i = 0; i < 32; i += 8)
        t[ty + i][tx] = src[(size_t)(s0 + ty + i) * Dd + d0 + tx];
    __syncthreads();
#pragma unroll
    for (int i = 0; i < 32; i += 8)
        dst[(size_t)(d0 + ty + i) * Ss + s0 + tx] = t[tx][ty + i];
}

// ===========================================================================
// fp16 GEMM (QKV / proj): C = A*B.  256 thr, tile 128x128, 32 K-chunks.
// Pitch 40 halfs (conflict-free ldmatrix + staging).
// ===========================================================================
#define GP 40
#define G_A 0
#define G_B 5120

struct GemmAcc { float a[4][4][4]; };

__device__ __forceinline__ void gemm128_mainloop(
    const __half* __restrict__ A_g, const __half* __restrict__ B_g,
    __half* sm, GemmAcc& C)
{
    const int tid = threadIdx.x;
    const int wid = tid >> 5, lane = tid & 31;
    const int grp = lane >> 3, rr = lane & 7;
    const int wm = (wid & 1) * 64, wn = (wid >> 1) * 32;
    const int r0 = tid >> 2, c0 = (tid & 3) * 8;

    uint4 rA[2], rB[2];
#pragma unroll
    for (int j = 0; j < 2; j++) {
        size_t go = (size_t)(r0 + j * 64) * Ee + c0;
        rA[j] = *(const uint4*)(A_g + go);
        rB[j] = *(const uint4*)(B_g + go);
    }

    const int aoff = (wm + (grp & 1) * 8 + rr) * GP + (grp >> 1) * 8;
    const int boff = (wn + rr) * GP + grp * 8;

    for (int kc = 0; kc < 32; kc++) {
#pragma unroll
        for (int j = 0; j < 2; j++) {
            int si = (r0 + j * 64) * GP + c0;
            *(uint4*)(sm + G_A + si) = rA[j];
            *(uint4*)(sm + G_B + si) = rB[j];
        }
        __syncthreads();

        if (kc < 31) {
            int k0n = (kc + 1) * 32;
#pragma unroll
            for (int j = 0; j < 2; j++) {
                size_t go = (size_t)(r0 + j * 64) * Ee + k0n + c0;
                rA[j] = *(const uint4*)(A_g + go);
                rB[j] = *(const uint4*)(B_g + go);
            }
        }

        uint32_t bf[4][4];
#pragma unroll
        for (int nf = 0; nf < 4; nf++)
            ldsm4(bf[nf], lds_addr(sm + G_B + boff + nf * 8 * GP));
#pragma unroll
        for (int ks = 0; ks < 2; ks++) {
            uint32_t af[4][4];
#pragma unroll
            for (int mf = 0; mf < 4; mf++)
                ldsm4(af[mf], lds_addr(sm + G_A + aoff + mf * 16 * GP + ks * 16));
#pragma unroll
            for (int nf = 0; nf < 4; nf++) {
                uint32_t b0 = bf[nf][ks * 2], b1 = bf[nf][ks * 2 + 1];
#pragma unroll
                for (int mf = 0; mf < 4; mf++)
                    mma_f16(C.a[mf][nf], af[mf], b0, b1);
            }
        }
        __syncthreads();
    }
}

__global__ __launch_bounds__(256) void gemm_qkv() {
    __shared__ __half sm[10240];
    const int tid = threadIdx.x;
    const int wid = tid >> 5, lane = tid & 31;
    const int g = lane >> 2, t4 = lane & 3;
    const int wm = (wid & 1) * 64, wn = (wid >> 1) * 32;
    const int n0 = blockIdx.x * 128, m0 = blockIdx.y * 128, z = blockIdx.z;

    GemmAcc C = {};
    gemm128_mainloop(g_xh + (size_t)m0 * Ee,
                     g_wT + ((size_t)z * Ee + n0) * Ee, sm, C);

    const float qs = (z == 0) ? 0.125f : 1.0f;
    __half* Oh = (z == 0) ? g_Qh : (z == 1) ? g_Kh : g_Vh;

#pragma unroll
    for (int mf = 0; mf < 4; mf++)
#pragma unroll
        for (int nf = 0; nf < 4; nf++) {
            int col = n0 + wn + nf * 8 + t4 * 2;
            int h = col >> 6, d = col & 63;
#pragma unroll
            for (int hi = 0; hi < 2; hi++) {
                int row = m0 + wm + mf * 16 + g + hi * 8;
                int b = row >> 11, s = row & (Ss - 1);
                size_t di = (((size_t)(b * Hh + h)) * Ss + s) * Dd + d;
                *(__half2*)&Oh[di] =
                    __half2(__float2half(C.a[mf][nf][hi * 2] * qs),
                            __float2half(C.a[mf][nf][hi * 2 + 1] * qs));
            }
        }
}

__global__ __launch_bounds__(256) void gemm_proj(const float* __restrict__ bo,
                                                 float* __restrict__ out) {
    __shared__ __half sm[10240];
    const int tid = threadIdx.x;
    const int wid = tid >> 5, lane = tid & 31;
    const int g = lane >> 2, t4 = lane & 3;
    const int wm = (wid & 1) * 64, wn = (wid >> 1) * 32;
    const int n0 = blockIdx.x * 128, m0 = blockIdx.y * 128;

    GemmAcc C = {};
    gemm128_mainloop(g_Oh + (size_t)m0 * Ee,
                     g_wT + ((size_t)3 * Ee + n0) * Ee, sm, C);

#pragma unroll
    for (int mf = 0; mf < 4; mf++)
#pragma unroll
        for (int nf = 0; nf < 4; nf++) {
            int col = n0 + wn + nf * 8 + t4 * 2;
            float2 bias = *(const float2*)&bo[col];
#pragma unroll
            for (int hi = 0; hi < 2; hi++) {
                int row = m0 + wm + mf * 16 + g + hi * 8;
                *(float2*)&out[(size_t)row * Ee + col] =
                    make_float2(C.a[mf][nf][hi * 2] + bias.x,
                                C.a[mf][nf][hi * 2 + 1] + bias.y);
            }
        }
}

// ===========================================================================
// Attention: fp16 flash attention, 8 warps x 16 q-rows, fp32 accum/softmax.
// Q register-resident; Q smem region reused for P. Pitch 72 halfs.
// ===========================================================================
#define AP2 72
#define A_P 0
#define A_K 9216
#define A_V 13824

__global__ __launch_bounds__(256) void attn_f16() {
    __shared__ __half sm[18432];
    const int tid = threadIdx.x;
    const int wid = tid >> 5, lane = tid & 31;
    const int g = lane >> 2, t4 = lane & 3;
    const int grp = lane >> 3, rr = lane & 7;
    const int bh = blockIdx.y;
    const int qb = gridDim.x - 1 - blockIdx.x;   // heavy tiles first
    const int q0 = qb * 128;
    const int wrow = wid * 16;

    const __half* Qg = g_Qh + (size_t)bh * Ss * Dd;
    const __half* Kg = g_Kh + (size_t)bh * Ss * Dd;
    const __half* Vg = g_Vt + (size_t)bh * Dd * Ss;

    // stage Q into (future) P region: 128 x 64
#pragma unroll
    for (int t = 0; t < 4; t++) {
        int slot = t * 256 + tid;
        int r = slot >> 3, c = (slot & 7) * 8;
        *(uint4*)(sm + A_P + r * AP2 + c) =
            *(const uint4*)(Qg + (size_t)(q0 + r) * Dd + c);
    }
    __syncthreads();

    const int qoff = (wrow + (grp & 1) * 8 + rr) * AP2 + (grp >> 1) * 8;
    uint32_t qf[4][4];
#pragma unroll
    for (int ks = 0; ks < 4; ks++)
        ldsm4(qf[ks], lds_addr(sm + A_P + qoff + ks * 16));

    const int boff = rr * AP2 + grp * 8;

    float m_i[2] = {-1e30f, -1e30f}, l_i[2] = {0.f, 0.f};
    float o[8][4] = {};

    const int ktmax = 2 * qb + 2;
    for (int kt = 0; kt < ktmax; kt++) {
        const int k0 = kt * 64;
        __syncthreads();   // prior PV reads (and Q frag loads, iter 0) done
#pragma unroll
        for (int t = 0; t < 4; t++) {
            int slot = t * 256 + tid;
            int tensor = slot >> 9, s2 = slot & 511;
            int r = s2 >> 3, c = (s2 & 7) * 8;
            const __half* src = tensor ? Vg + (size_t)r * Ss + k0 + c
                                       : Kg + (size_t)(k0 + r) * Dd + c;
            *(uint4*)(sm + (tensor ? A_V : A_K) + r * AP2 + c) = *(const uint4*)src;
        }
        __syncthreads();

        // ---- S = Q K^T ----
        float sc[8][4] = {};
#pragma unroll
        for (int nf = 0; nf < 8; nf++) {
            uint32_t k8[8];
            ldsm4(k8,     lds_addr(sm + A_K + boff + nf * 8 * AP2));
            ldsm4(k8 + 4, lds_addr(sm + A_K + boff + nf * 8 * AP2 + 32));
#pragma unroll
            for (int ks = 0; ks < 4; ks++)
                mma_f16(sc[nf], qf[ks], k8[ks * 2], k8[ks * 2 + 1]);
        }

        // ---- causal mask ----
        if (kt >= 2 * qb) {
#pragma unroll
            for (int nf = 0; nf < 8; nf++)
#pragma unroll
                for (int j = 0; j < 4; j++) {
                    int col = k0 + nf * 8 + t4 * 2 + (j & 1);
                    int row = q0 + wrow + g + (j >> 1) * 8;
                    if (col > row) sc[nf][j] = -1e30f;
                }
        }

        // ---- online softmax ----
#pragma unroll
        for (int hi = 0; hi < 2; hi++) {
            const int j0 = hi * 2;
            float mrow = -1e30f;
#pragma unroll
            for (int nf = 0; nf < 8; nf++)
                mrow = fmaxf(mrow, fmaxf(sc[nf][j0], sc[nf][j0 + 1]));
            mrow = fmaxf(mrow, __shfl_xor_sync(0xffffffffu, mrow, 1));
            mrow = fmaxf(mrow, __shfl_xor_sync(0xffffffffu, mrow, 2));
            float mnew = fmaxf(m_i[hi], mrow);
            float corr = __expf(m_i[hi] - mnew);
            m_i[hi] = mnew;
            float ps = 0.f;
#pragma unroll
            for (int nf = 0; nf < 8; nf++) {
                float e0 = __expf(sc[nf][j0] - mnew);
                float e1 = __expf(sc[nf][j0 + 1] - mnew);
                sc[nf][j0] = e0; sc[nf][j0 + 1] = e1;
                ps += e0 + e1;
            }
            ps += __shfl_xor_sync(0xffffffffu, ps, 1);
            ps += __shfl_xor_sync(0xffffffffu, ps, 2);
            l_i[hi] = l_i[hi] * corr + ps;
#pragma unroll
            for (int nf = 0; nf < 8; nf++) {
                o[nf][j0] *= corr;
                o[nf][j0 + 1] *= corr;
            }
        }

        // ---- P -> smem (warp-private rows) ----
#pragma unroll
        for (int nf = 0; nf < 8; nf++) {
            int col = nf * 8 + t4 * 2;
            *(__half2*)(sm + A_P + (wrow + g) * AP2 + col) =
                __half2(__float2half(sc[nf][0]), __float2half(sc[nf][1]));
            *(__half2*)(sm + A_P + (wrow + g + 8) * AP2 + col) =
                __half2(__float2half(sc[nf][2]), __float2half(sc[nf][3]));
        }
        __syncwarp();

        // ---- O += P V ----
        uint32_t pf[4][4];
#pragma unroll
        for (int ks = 0; ks < 4; ks++)
            ldsm4(pf[ks], lds_addr(sm + A_P + qoff + ks * 16));
#pragma unroll
        for (int nf = 0; nf < 8; nf++) {
            uint32_t v8[8];
            ldsm4(v8,     lds_addr(sm + A_V + boff + nf * 8 * AP2));
            ldsm4(v8 + 4, lds_addr(sm + A_V + boff + nf * 8 * AP2 + 32));
#pragma unroll
            for (int ks = 0; ks < 4; ks++)
                mma_f16(o[nf], pf[ks], v8[ks * 2], v8[ks * 2 + 1]);
        }
    }

    // ---- epilogue: O/l -> fp16, proj layout [b*S+s][h*64+d] ----
    const int b = bh >> 4, h = bh & 15;
    float inv_lo = 1.0f / l_i[0];
    float inv_hi = 1.0f / l_i[1];
#pragma unroll
    for (int nf = 0; nf < 8; nf++) {
        int srow = q0 + wrow + g;
        int col = h * 64 + nf * 8 + t4 * 2;
        size_t r0i = ((size_t)b * Ss + srow) * Ee + col;
        size_t r1i = ((size_t)b * Ss + srow + 8) * Ee + col;
        *(__half2*)&g_Oh[r0i] =
            __half2(__float2half(o[nf][0] * inv_lo), __float2half(o[nf][1] * inv_lo));
        *(__half2*)&g_Oh[r1i] =
            __half2(__float2half(o[nf][2] * inv_hi), __float2half(o[nf][3] * inv_hi));
    }
}

// ---------------------------------------------------------------------------
extern "C" void kernel_launch(void* const* d_in, const int* in_sizes, int n_in,
                              void* d_out, int out_size)
{
    const float* x  = (const float*)d_in[0];
    const float* Wq = (const float*)d_in[1];
    const float* Wk = (const float*)d_in[2];
    const float* Wv = (const float*)d_in[3];
    const float* Wo = (const float*)d_in[4];
    const float* bo = (const float*)d_in[5];
    float* out = (float*)d_out;

    round_x<<<16384, 256>>>(x);
    wsplit<<<dim3(32, 32, 4), dim3(32, 8)>>>(Wq, Wk, Wv, Wo);
    gemm_qkv<<<dim3(8, 32, 3), 256>>>();
    vtrans<<<dim3(64, 2, 32), dim3(32, 8)>>>();
    attn_f16<<<dim3(16, 32), 256>>>();
    gemm_proj<<<dim3(8, 32), 256>>>(bo, out);
}

// round 12
// speedup vs baseline: 5.6565x; 1.1654x over previous
#include <cuda_runtime.h>
#include <cuda_fp16.h>
#include <cstdint>

#define Ss 2048
#define Ee 1024
#define Hh 16
#define Dd 64

// ---------------- device scratch ------------------------------------------
__device__ __half g_xh[(size_t)4096 * 1024];
__device__ __half g_wT[(size_t)4 * 1024 * 1024];    // [mat][n][k]
__device__ __half g_Qh[(size_t)32 * Ss * Dd];       // [bh][s][d], pre-scaled
__device__ __half g_Kh[(size_t)32 * Ss * Dd];
__device__ __half g_Vh[(size_t)32 * Ss * Dd];
__device__ __half g_Vt[(size_t)32 * Dd * Ss];       // [bh][d][s]
__device__ __half g_Oh[(size_t)4096 * 1024];        // [b*S+s][h*64+d]

// ---------------- helpers --------------------------------------------------
__device__ __forceinline__ void mma_f16(float c[4],
                                        const uint32_t a[4],
                                        uint32_t b0, uint32_t b1) {
    asm volatile(
        "mma.sync.aligned.m16n8k16.row.col.f32.f16.f16.f32 "
        "{%0,%1,%2,%3},{%4,%5,%6,%7},{%8,%9},{%0,%1,%2,%3};"
        : "+f"(c[0]), "+f"(c[1]), "+f"(c[2]), "+f"(c[3])
        : "r"(a[0]), "r"(a[1]), "r"(a[2]), "r"(a[3]), "r"(b0), "r"(b1));
}
__device__ __forceinline__ uint32_t lds_addr(const void* p) {
    return (uint32_t)__cvta_generic_to_shared(p);
}
__device__ __forceinline__ void ldsm4(uint32_t r[4], uint32_t a) {
    asm volatile("ldmatrix.sync.aligned.m8n8.x4.shared.b16 {%0,%1,%2,%3}, [%4];"
        : "=r"(r[0]), "=r"(r[1]), "=r"(r[2]), "=r"(r[3]) : "r"(a));
}
__device__ __forceinline__ void cp16(__half* dst_sm, const __half* src) {
    asm volatile("cp.async.cg.shared.global [%0], [%1], 16;"
        :: "r"(lds_addr(dst_sm)), "l"(src));
}
#define CP_COMMIT() asm volatile("cp.async.commit_group;" ::: "memory")
#define CP_WAIT1()  asm volatile("cp.async.wait_group 1;" ::: "memory")
#define CP_WAIT0()  asm volatile("cp.async.wait_group 0;" ::: "memory")

// ===========================================================================
// Pre-passes
// ===========================================================================
__global__ __launch_bounds__(256) void round_x(const float* __restrict__ src) {
    int i = blockIdx.x * 256 + threadIdx.x;
    g_xh[i] = __float2half(src[i]);
}

__global__ __launch_bounds__(256) void wsplit(
    const float* __restrict__ Wq, const float* __restrict__ Wk,
    const float* __restrict__ Wv, const float* __restrict__ Wo)
{
    __shared__ float t[32][33];
    const int z = blockIdx.z;
    const float* W = (z == 0) ? Wq : (z == 1) ? Wk : (z == 2) ? Wv : Wo;
    const int tx = threadIdx.x, ty = threadIdx.y;
    const int bx = blockIdx.x, by = blockIdx.y;
#pragma unroll
    for (int i = 0; i < 32; i += 8)
        t[ty + i][tx] = W[(size_t)(by * 32 + ty + i) * Ee + bx * 32 + tx];
    __syncthreads();
    const size_t base = (size_t)z * Ee * Ee;
#pragma unroll
    for (int i = 0; i < 32; i += 8) {
        int n = bx * 32 + ty + i, k = by * 32 + tx;
        g_wT[base + (size_t)n * Ee + k] = __float2half(t[tx][ty + i]);
    }
}

__global__ __launch_bounds__(256) void vtrans() {
    __shared__ __half t[32][33];
    const int bh = blockIdx.z;
    const __half* src = g_Vh + (size_t)bh * Ss * Dd;
    __half* dst = g_Vt + (size_t)bh * Dd * Ss;
    const int tx = threadIdx.x, ty = threadIdx.y;
    const int s0 = blockIdx.x * 32, d0 = blockIdx.y * 32;
#pragma unroll
    for (int i = 0; i < 32; i += 8)
        t[ty + i][tx] = src[(size_t)(s0 + ty + i) * Dd + d0 + tx];
    __syncthreads();
#pragma unroll
    for (int i = 0; i < 32; i += 8)
        dst[(size_t)(d0 + ty + i) * Ss + s0 + tx] = t[tx][ty + i];
}

// ===========================================================================
// fp16 GEMM: 3-stage cp.async pipeline, 1 sync/chunk. Tile 128x128, Kc=32.
// Pitch 40 halfs = 80B (16B-aligned, conflict-free ldmatrix/staging).
// ===========================================================================
#define GP 40
#define G_A 0
#define G_B 5120
#define GSTG 10240                      // halfs per stage
#define GEMM_SMEM (3 * GSTG * 2)        // 60 KB

struct GemmAcc { float a[4][4][4]; };

__device__ __forceinline__ void gemm128_mainloop(
    const __half* __restrict__ A_g, const __half* __restrict__ B_g,
    __half* sm, GemmAcc& C)
{
    const int tid = threadIdx.x;
    const int wid = tid >> 5, lane = tid & 31;
    const int grp = lane >> 3, rr = lane & 7;
    const int wm = (wid & 1) * 64, wn = (wid >> 1) * 32;
    const int r0 = tid >> 2, c0 = (tid & 3) * 8;

    const int aoff = (wm + (grp & 1) * 8 + rr) * GP + (grp >> 1) * 8;
    const int boff = (wn + rr) * GP + grp * 8;

    auto issue = [&](int kc) {
        __half* buf = sm + (kc % 3) * GSTG;
        const int k0 = kc * 32;
#pragma unroll
        for (int j = 0; j < 2; j++) {
            int r = r0 + j * 64;
            cp16(buf + G_A + r * GP + c0, A_g + (size_t)r * Ee + k0 + c0);
            cp16(buf + G_B + r * GP + c0, B_g + (size_t)r * Ee + k0 + c0);
        }
        CP_COMMIT();
    };

    issue(0);
    issue(1);

    for (int kc = 0; kc < 32; kc++) {
        if (kc < 31) CP_WAIT1(); else CP_WAIT0();
        __syncthreads();                 // stage kc visible; all past stage kc-1
        if (kc + 2 < 32) issue(kc + 2);  // overwrites stage (kc-1)%3: safe

        __half* buf = sm + (kc % 3) * GSTG;
        uint32_t bf[4][4];
#pragma unroll
        for (int nf = 0; nf < 4; nf++)
            ldsm4(bf[nf], lds_addr(buf + G_B + boff + nf * 8 * GP));
#pragma unroll
        for (int ks = 0; ks < 2; ks++) {
            uint32_t af[4][4];
#pragma unroll
            for (int mf = 0; mf < 4; mf++)
                ldsm4(af[mf], lds_addr(buf + G_A + aoff + mf * 16 * GP + ks * 16));
#pragma unroll
            for (int nf = 0; nf < 4; nf++) {
                uint32_t b0 = bf[nf][ks * 2], b1 = bf[nf][ks * 2 + 1];
#pragma unroll
                for (int mf = 0; mf < 4; mf++)
                    mma_f16(C.a[mf][nf], af[mf], b0, b1);
            }
        }
    }
}

__global__ __launch_bounds__(256) void gemm_qkv() {
    extern __shared__ __half smg[];
    const int tid = threadIdx.x;
    const int wid = tid >> 5, lane = tid & 31;
    const int g = lane >> 2, t4 = lane & 3;
    const int wm = (wid & 1) * 64, wn = (wid >> 1) * 32;
    const int n0 = blockIdx.x * 128, m0 = blockIdx.y * 128, z = blockIdx.z;

    GemmAcc C = {};
    gemm128_mainloop(g_xh + (size_t)m0 * Ee,
                     g_wT + ((size_t)z * Ee + n0) * Ee, smg, C);

    const float qs = (z == 0) ? 0.125f : 1.0f;
    __half* Oh = (z == 0) ? g_Qh : (z == 1) ? g_Kh : g_Vh;

#pragma unroll
    for (int mf = 0; mf < 4; mf++)
#pragma unroll
        for (int nf = 0; nf < 4; nf++) {
            int col = n0 + wn + nf * 8 + t4 * 2;
            int h = col >> 6, d = col & 63;
#pragma unroll
            for (int hi = 0; hi < 2; hi++) {
                int row = m0 + wm + mf * 16 + g + hi * 8;
                int b = row >> 11, s = row & (Ss - 1);
                size_t di = (((size_t)(b * Hh + h)) * Ss + s) * Dd + d;
                *(__half2*)&Oh[di] =
                    __half2(__float2half(C.a[mf][nf][hi * 2] * qs),
                            __float2half(C.a[mf][nf][hi * 2 + 1] * qs));
            }
        }
}

__global__ __launch_bounds__(256) void gemm_proj(const float* __restrict__ bo,
                                                 float* __restrict__ out) {
    extern __shared__ __half smg[];
    const int tid = threadIdx.x;
    const int wid = tid >> 5, lane = tid & 31;
    const int g = lane >> 2, t4 = lane & 3;
    const int wm = (wid & 1) * 64, wn = (wid >> 1) * 32;
    const int n0 = blockIdx.x * 128, m0 = blockIdx.y * 128;

    GemmAcc C = {};
    gemm128_mainloop(g_Oh + (size_t)m0 * Ee,
                     g_wT + ((size_t)3 * Ee + n0) * Ee, smg, C);

#pragma unroll
    for (int mf = 0; mf < 4; mf++)
#pragma unroll
        for (int nf = 0; nf < 4; nf++) {
            int col = n0 + wn + nf * 8 + t4 * 2;
            float2 bias = *(const float2*)&bo[col];
#pragma unroll
            for (int hi = 0; hi < 2; hi++) {
                int row = m0 + wm + mf * 16 + g + hi * 8;
                *(float2*)&out[(size_t)row * Ee + col] =
                    make_float2(C.a[mf][nf][hi * 2] + bias.x,
                                C.a[mf][nf][hi * 2 + 1] + bias.y);
            }
        }
}

// ===========================================================================
// Attention: fp16 flash attention, 3-stage cp.async K/V pipeline,
// 8 warps x 16 q-rows, 1 syncthreads per k-tile. Pitch 72 halfs = 144B.
// ===========================================================================
#define AP2 72
#define A_P 0
#define ASTG 4608                        // 64x72 halfs per tensor tile
#define A_S0 9216                        // stages base
#define ATTN_SMEM ((9216 + 3 * 2 * ASTG) * 2)   // 72 KB

__global__ __launch_bounds__(256) void attn_f16() {
    extern __shared__ __half sma[];
    const int tid = threadIdx.x;
    const int wid = tid >> 5, lane = tid & 31;
    const int g = lane >> 2, t4 = lane & 3;
    const int grp = lane >> 3, rr = lane & 7;
    const int bh = blockIdx.y;
    const int qb = gridDim.x - 1 - blockIdx.x;   // heavy tiles first
    const int q0 = qb * 128;
    const int wrow = wid * 16;

    const __half* Qg = g_Qh + (size_t)bh * Ss * Dd;
    const __half* Kg = g_Kh + (size_t)bh * Ss * Dd;
    const __half* Vg = g_Vt + (size_t)bh * Dd * Ss;

    // stage Q into (future) P region: 128 x 64
#pragma unroll
    for (int t = 0; t < 4; t++) {
        int slot = t * 256 + tid;
        int r = slot >> 3, c = (slot & 7) * 8;
        *(uint4*)(sma + A_P + r * AP2 + c) =
            *(const uint4*)(Qg + (size_t)(q0 + r) * Dd + c);
    }

    const int ktmax = 2 * qb + 2;

    auto issue = [&](int kt) {
        __half* buf = sma + A_S0 + (kt % 3) * 2 * ASTG;
        const int k0 = kt * 64;
#pragma unroll
        for (int t = 0; t < 2; t++) {
            int slot = t * 256 + tid;
            int r = slot >> 3, c = (slot & 7) * 8;
            cp16(buf + r * AP2 + c, Kg + (size_t)(k0 + r) * Dd + c);
            cp16(buf + ASTG + r * AP2 + c, Vg + (size_t)r * Ss + k0 + c);
        }
        CP_COMMIT();
    };

    issue(0);
    issue(1);           // ktmax >= 2 always

    __syncthreads();    // Q staged before frag loads
    const int qoff = (wrow + (grp & 1) * 8 + rr) * AP2 + (grp >> 1) * 8;
    uint32_t qf[4][4];
#pragma unroll
    for (int ks = 0; ks < 4; ks++)
        ldsm4(qf[ks], lds_addr(sma + A_P + qoff + ks * 16));

    const int boff = rr * AP2 + grp * 8;

    float m_i[2] = {-1e30f, -1e30f}, l_i[2] = {0.f, 0.f};
    float o[8][4] = {};

    for (int kt = 0; kt < ktmax; kt++) {
        const int k0 = kt * 64;
        if (kt + 1 < ktmax) CP_WAIT1(); else CP_WAIT0();
        __syncthreads();                       // stage kt visible; all past kt-1
        if (kt + 2 < ktmax) issue(kt + 2);     // overwrites stage (kt-1)%3

        __half* kbuf = sma + A_S0 + (kt % 3) * 2 * ASTG;
        __half* vbuf = kbuf + ASTG;

        // ---- S = Q K^T ----
        float sc[8][4] = {};
#pragma unroll
        for (int nf = 0; nf < 8; nf++) {
            uint32_t k8[8];
            ldsm4(k8,     lds_addr(kbuf + boff + nf * 8 * AP2));
            ldsm4(k8 + 4, lds_addr(kbuf + boff + nf * 8 * AP2 + 32));
#pragma unroll
            for (int ks = 0; ks < 4; ks++)
                mma_f16(sc[nf], qf[ks], k8[ks * 2], k8[ks * 2 + 1]);
        }

        // ---- causal mask ----
        if (kt >= 2 * qb) {
#pragma unroll
            for (int nf = 0; nf < 8; nf++)
#pragma unroll
                for (int j = 0; j < 4; j++) {
                    int col = k0 + nf * 8 + t4 * 2 + (j & 1);
                    int row = q0 + wrow + g + (j >> 1) * 8;
                    if (col > row) sc[nf][j] = -1e30f;
                }
        }

        // ---- online softmax ----
#pragma unroll
        for (int hi = 0; hi < 2; hi++) {
            const int j0 = hi * 2;
            float mrow = -1e30f;
#pragma unroll
            for (int nf = 0; nf < 8; nf++)
                mrow = fmaxf(mrow, fmaxf(sc[nf][j0], sc[nf][j0 + 1]));
            mrow = fmaxf(mrow, __shfl_xor_sync(0xffffffffu, mrow, 1));
            mrow = fmaxf(mrow, __shfl_xor_sync(0xffffffffu, mrow, 2));
            float mnew = fmaxf(m_i[hi], mrow);
            float corr = __expf(m_i[hi] - mnew);
            m_i[hi] = mnew;
            float ps = 0.f;
#pragma unroll
            for (int nf = 0; nf < 8; nf++) {
                float e0 = __expf(sc[nf][j0] - mnew);
                float e1 = __expf(sc[nf][j0 + 1] - mnew);
                sc[nf][j0] = e0; sc[nf][j0 + 1] = e1;
                ps += e0 + e1;
            }
            ps += __shfl_xor_sync(0xffffffffu, ps, 1);
            ps += __shfl_xor_sync(0xffffffffu, ps, 2);
            l_i[hi] = l_i[hi] * corr + ps;
#pragma unroll
            for (int nf = 0; nf < 8; nf++) {
                o[nf][j0] *= corr;
                o[nf][j0 + 1] *= corr;
            }
        }

        // ---- P -> smem (warp-private rows) ----
#pragma unroll
        for (int nf = 0; nf < 8; nf++) {
            int col = nf * 8 + t4 * 2;
            *(__half2*)(sma + A_P + (wrow + g) * AP2 + col) =
                __half2(__float2half(sc[nf][0]), __float2half(sc[nf][1]));
            *(__half2*)(sma + A_P + (wrow + g + 8) * AP2 + col) =
                __half2(__float2half(sc[nf][2]), __float2half(sc[nf][3]));
        }
        __syncwarp();

        // ---- O += P V ----
        uint32_t pf[4][4];
#pragma unroll
        for (int ks = 0; ks < 4; ks++)
            ldsm4(pf[ks], lds_addr(sma + A_P + qoff + ks * 16));
#pragma unroll
        for (int nf = 0; nf < 8; nf++) {
            uint32_t v8[8];
            ldsm4(v8,     lds_addr(vbuf + boff + nf * 8 * AP2));
            ldsm4(v8 + 4, lds_addr(vbuf + boff + nf * 8 * AP2 + 32));
#pragma unroll
            for (int ks = 0; ks < 4; ks++)
                mma_f16(o[nf], pf[ks], v8[ks * 2], v8[ks * 2 + 1]);
        }
    }

    // ---- epilogue: O/l -> fp16, proj layout [b*S+s][h*64+d] ----
    const int b = bh >> 4, h = bh & 15;
    float inv_lo = 1.0f / l_i[0];
    float inv_hi = 1.0f / l_i[1];
#pragma unroll
    for (int nf = 0; nf < 8; nf++) {
        int srow = q0 + wrow + g;
        int col = h * 64 + nf * 8 + t4 * 2;
        size_t r0i = ((size_t)b * Ss + srow) * Ee + col;
        size_t r1i = ((size_t)b * Ss + srow + 8) * Ee + col;
        *(__half2*)&g_Oh[r0i] =
            __half2(__float2half(o[nf][0] * inv_lo), __float2half(o[nf][1] * inv_lo));
        *(__half2*)&g_Oh[r1i] =
            __half2(__float2half(o[nf][2] * inv_hi), __float2half(o[nf][3] * inv_hi));
    }
}

// ---------------------------------------------------------------------------
extern "C" void kernel_launch(void* const* d_in, const int* in_sizes, int n_in,
                              void* d_out, int out_size)
{
    const float* x  = (const float*)d_in[0];
    const float* Wq = (const float*)d_in[1];
    const float* Wk = (const float*)d_in[2];
    const float* Wv = (const float*)d_in[3];
    const float* Wo = (const float*)d_in[4];
    const float* bo = (const float*)d_in[5];
    float* out = (float*)d_out;

    cudaFuncSetAttribute(gemm_qkv,  cudaFuncAttributeMaxDynamicSharedMemorySize, GEMM_SMEM);
    cudaFuncSetAttribute(gemm_proj, cudaFuncAttributeMaxDynamicSharedMemorySize, GEMM_SMEM);
    cudaFuncSetAttribute(attn_f16,  cudaFuncAttributeMaxDynamicSharedMemorySize, ATTN_SMEM);

    round_x<<<16384, 256>>>(x);
    wsplit<<<dim3(32, 32, 4), dim3(32, 8)>>>(Wq, Wk, Wv, Wo);
    gemm_qkv<<<dim3(8, 32, 3), 256, GEMM_SMEM>>>();
    vtrans<<<dim3(64, 2, 32), dim3(32, 8)>>>();
    attn_f16<<<dim3(16, 32), 256, ATTN_SMEM>>>();
    gemm_proj<<<dim3(8, 32), 256, GEMM_SMEM>>>(bo, out);
}

// round 13
// speedup vs baseline: 5.8227x; 1.0294x over previous
#include <cuda_runtime.h>
#include <cuda_fp16.h>
#include <cstdint>

#define Ss 2048
#define Ee 1024
#define Hh 16
#define Dd 64

// ---------------- device scratch ------------------------------------------
__device__ __half g_xh[(size_t)4096 * 1024];
__device__ __half g_wT[(size_t)4 * 1024 * 1024];    // [mat][n][k]
__device__ __half g_Qh[(size_t)32 * Ss * Dd];       // [bh][s][d], pre-scaled by 0.125*log2e
__device__ __half g_Kh[(size_t)32 * Ss * Dd];
__device__ __half g_Vh[(size_t)32 * Ss * Dd];
__device__ __half g_Oh[(size_t)4096 * 1024];        // [b*S+s][h*64+d]

// ---------------- helpers --------------------------------------------------
__device__ __forceinline__ void mma_f16(float c[4],
                                        const uint32_t a[4],
                                        uint32_t b0, uint32_t b1) {
    asm volatile(
        "mma.sync.aligned.m16n8k16.row.col.f32.f16.f16.f32 "
        "{%0,%1,%2,%3},{%4,%5,%6,%7},{%8,%9},{%0,%1,%2,%3};"
        : "+f"(c[0]), "+f"(c[1]), "+f"(c[2]), "+f"(c[3])
        : "r"(a[0]), "r"(a[1]), "r"(a[2]), "r"(a[3]), "r"(b0), "r"(b1));
}
__device__ __forceinline__ uint32_t lds_addr(const void* p) {
    return (uint32_t)__cvta_generic_to_shared(p);
}
__device__ __forceinline__ void ldsm4(uint32_t r[4], uint32_t a) {
    asm volatile("ldmatrix.sync.aligned.m8n8.x4.shared.b16 {%0,%1,%2,%3}, [%4];"
        : "=r"(r[0]), "=r"(r[1]), "=r"(r[2]), "=r"(r[3]) : "r"(a));
}
__device__ __forceinline__ void ldsm4t(uint32_t r[4], uint32_t a) {
    asm volatile("ldmatrix.sync.aligned.m8n8.x4.trans.shared.b16 {%0,%1,%2,%3}, [%4];"
        : "=r"(r[0]), "=r"(r[1]), "=r"(r[2]), "=r"(r[3]) : "r"(a));
}
__device__ __forceinline__ float ex2f(float x) {
    float r;
    asm("ex2.approx.f32 %0, %1;" : "=f"(r) : "f"(x));
    return r;
}
__device__ __forceinline__ void cp16(__half* dst_sm, const __half* src) {
    asm volatile("cp.async.cg.shared.global [%0], [%1], 16;"
        :: "r"(lds_addr(dst_sm)), "l"(src));
}
#define CP_COMMIT() asm volatile("cp.async.commit_group;" ::: "memory")
#define CP_WAIT1()  asm volatile("cp.async.wait_group 1;" ::: "memory")
#define CP_WAIT0()  asm volatile("cp.async.wait_group 0;" ::: "memory")

// ===========================================================================
// Fused pre-pass: z<4 -> transpose+round W_z tiles; z>=4 -> round x chunk.
// Block (32,8).
// ===========================================================================
__global__ __launch_bounds__(256) void prepass(
    const float* __restrict__ x,
    const float* __restrict__ Wq, const float* __restrict__ Wk,
    const float* __restrict__ Wv, const float* __restrict__ Wo)
{
    const int tx = threadIdx.x, ty = threadIdx.y;
    const int z = blockIdx.z;
    if (z >= 4) {
        int i = ((z - 4) * 1024 + blockIdx.y * 32 + blockIdx.x) * 256 + ty * 32 + tx;
        g_xh[i] = __float2half(x[i]);
        return;
    }
    __shared__ float t[32][33];
    const float* W = (z == 0) ? Wq : (z == 1) ? Wk : (z == 2) ? Wv : Wo;
    const int bx = blockIdx.x, by = blockIdx.y;
#pragma unroll
    for (int i = 0; i < 32; i += 8)
        t[ty + i][tx] = W[(size_t)(by * 32 + ty + i) * Ee + bx * 32 + tx];
    __syncthreads();
    const size_t base = (size_t)z * Ee * Ee;
#pragma unroll
    for (int i = 0; i < 32; i += 8) {
        int n = bx * 32 + ty + i, k = by * 32 + tx;
        g_wT[base + (size_t)n * Ee + k] = __float2half(t[tx][ty + i]);
    }
}

// ===========================================================================
// fp16 GEMM: 3-stage cp.async pipeline, 1 sync/chunk. Tile 128x128, Kc=32.
// Pitch 40 halfs = 80B.
// ===========================================================================
#define GP 40
#define G_A 0
#define G_B 5120
#define GSTG 10240
#define GEMM_SMEM (3 * GSTG * 2)        // 60 KB

struct GemmAcc { float a[4][4][4]; };

__device__ __forceinline__ void gemm128_mainloop(
    const __half* __restrict__ A_g, const __half* __restrict__ B_g,
    __half* sm, GemmAcc& C)
{
    const int tid = threadIdx.x;
    const int wid = tid >> 5, lane = tid & 31;
    const int grp = lane >> 3, rr = lane & 7;
    const int wm = (wid & 1) * 64, wn = (wid >> 1) * 32;
    const int r0 = tid >> 2, c0 = (tid & 3) * 8;

    const int aoff = (wm + (grp & 1) * 8 + rr) * GP + (grp >> 1) * 8;
    const int boff = (wn + rr) * GP + grp * 8;

    auto issue = [&](int kc) {
        __half* buf = sm + (kc % 3) * GSTG;
        const int k0 = kc * 32;
#pragma unroll
        for (int j = 0; j < 2; j++) {
            int r = r0 + j * 64;
            cp16(buf + G_A + r * GP + c0, A_g + (size_t)r * Ee + k0 + c0);
            cp16(buf + G_B + r * GP + c0, B_g + (size_t)r * Ee + k0 + c0);
        }
        CP_COMMIT();
    };

    issue(0);
    issue(1);

    for (int kc = 0; kc < 32; kc++) {
        if (kc < 31) CP_WAIT1(); else CP_WAIT0();
        __syncthreads();
        if (kc + 2 < 32) issue(kc + 2);

        __half* buf = sm + (kc % 3) * GSTG;
        uint32_t bf[4][4];
#pragma unroll
        for (int nf = 0; nf < 4; nf++)
            ldsm4(bf[nf], lds_addr(buf + G_B + boff + nf * 8 * GP));
#pragma unroll
        for (int ks = 0; ks < 2; ks++) {
            uint32_t af[4][4];
#pragma unroll
            for (int mf = 0; mf < 4; mf++)
                ldsm4(af[mf], lds_addr(buf + G_A + aoff + mf * 16 * GP + ks * 16));
#pragma unroll
            for (int nf = 0; nf < 4; nf++) {
                uint32_t b0 = bf[nf][ks * 2], b1 = bf[nf][ks * 2 + 1];
#pragma unroll
                for (int mf = 0; mf < 4; mf++)
                    mma_f16(C.a[mf][nf], af[mf], b0, b1);
            }
        }
    }
}

__global__ __launch_bounds__(256) void gemm_qkv() {
    extern __shared__ __half smg[];
    const int tid = threadIdx.x;
    const int wid = tid >> 5, lane = tid & 31;
    const int g = lane >> 2, t4 = lane & 3;
    const int wm = (wid & 1) * 64, wn = (wid >> 1) * 32;
    const int n0 = blockIdx.x * 128, m0 = blockIdx.y * 128, z = blockIdx.z;

    GemmAcc C = {};
    gemm128_mainloop(g_xh + (size_t)m0 * Ee,
                     g_wT + ((size_t)z * Ee + n0) * Ee, smg, C);

    // Q pre-scaled by D^-1/2 * log2(e) for exp2-domain softmax
    const float qs = (z == 0) ? 0.125f * 1.4426950408889634f : 1.0f;
    __half* Oh = (z == 0) ? g_Qh : (z == 1) ? g_Kh : g_Vh;

#pragma unroll
    for (int mf = 0; mf < 4; mf++)
#pragma unroll
        for (int nf = 0; nf < 4; nf++) {
            int col = n0 + wn + nf * 8 + t4 * 2;
            int h = col >> 6, d = col & 63;
#pragma unroll
            for (int hi = 0; hi < 2; hi++) {
                int row = m0 + wm + mf * 16 + g + hi * 8;
                int b = row >> 11, s = row & (Ss - 1);
                size_t di = (((size_t)(b * Hh + h)) * Ss + s) * Dd + d;
                *(__half2*)&Oh[di] =
                    __half2(__float2half(C.a[mf][nf][hi * 2] * qs),
                            __float2half(C.a[mf][nf][hi * 2 + 1] * qs));
            }
        }
}

__global__ __launch_bounds__(256) void gemm_proj(const float* __restrict__ bo,
                                                 float* __restrict__ out) {
    extern __shared__ __half smg[];
    const int tid = threadIdx.x;
    const int wid = tid >> 5, lane = tid & 31;
    const int g = lane >> 2, t4 = lane & 3;
    const int wm = (wid & 1) * 64, wn = (wid >> 1) * 32;
    const int n0 = blockIdx.x * 128, m0 = blockIdx.y * 128;

    GemmAcc C = {};
    gemm128_mainloop(g_Oh + (size_t)m0 * Ee,
                     g_wT + ((size_t)3 * Ee + n0) * Ee, smg, C);

#pragma unroll
    for (int mf = 0; mf < 4; mf++)
#pragma unroll
        for (int nf = 0; nf < 4; nf++) {
            int col = n0 + wn + nf * 8 + t4 * 2;
            float2 bias = *(const float2*)&bo[col];
#pragma unroll
            for (int hi = 0; hi < 2; hi++) {
                int row = m0 + wm + mf * 16 + g + hi * 8;
                *(float2*)&out[(size_t)row * Ee + col] =
                    make_float2(C.a[mf][nf][hi * 2] + bias.x,
                                C.a[mf][nf][hi * 2 + 1] + bias.y);
            }
        }
}

// ===========================================================================
// Attention: fp16 flash attention, exp2-domain softmax, 3-stage cp.async
// K/V pipeline. V staged natural [s][d]; PV B-frags via ldmatrix.trans.
// 8 warps x 16 q-rows. Pitch 72 halfs.
// ===========================================================================
#define AP2 72
#define A_P 0
#define ASTG 4608                        // 64x72 halfs per tensor tile
#define A_S0 9216
#define ATTN_SMEM ((9216 + 3 * 2 * ASTG) * 2)   // 72 KB

__global__ __launch_bounds__(256) void attn_f16() {
    extern __shared__ __half sma[];
    const int tid = threadIdx.x;
    const int wid = tid >> 5, lane = tid & 31;
    const int g = lane >> 2, t4 = lane & 3;
    const int grp = lane >> 3, rr = lane & 7;
    const int bh = blockIdx.y;
    const int qb = gridDim.x - 1 - blockIdx.x;   // heavy tiles first
    const int q0 = qb * 128;
    const int wrow = wid * 16;

    const __half* Qg = g_Qh + (size_t)bh * Ss * Dd;
    const __half* Kg = g_Kh + (size_t)bh * Ss * Dd;
    const __half* Vg = g_Vh + (size_t)bh * Ss * Dd;

    // stage Q into (future) P region: 128 x 64
#pragma unroll
    for (int t = 0; t < 4; t++) {
        int slot = t * 256 + tid;
        int r = slot >> 3, c = (slot & 7) * 8;
        *(uint4*)(sma + A_P + r * AP2 + c) =
            *(const uint4*)(Qg + (size_t)(q0 + r) * Dd + c);
    }

    const int ktmax = 2 * qb + 2;

    auto issue = [&](int kt) {
        __half* buf = sma + A_S0 + (kt % 3) * 2 * ASTG;
        const int k0 = kt * 64;
#pragma unroll
        for (int t = 0; t < 2; t++) {
            int slot = t * 256 + tid;
            int r = slot >> 3, c = (slot & 7) * 8;
            cp16(buf + r * AP2 + c, Kg + (size_t)(k0 + r) * Dd + c);
            cp16(buf + ASTG + r * AP2 + c, Vg + (size_t)(k0 + r) * Dd + c);
        }
        CP_COMMIT();
    };

    issue(0);
    issue(1);           // ktmax >= 2 always

    __syncthreads();    // Q staged before frag loads
    const int qoff = (wrow + (grp & 1) * 8 + rr) * AP2 + (grp >> 1) * 8;
    uint32_t qf[4][4];
#pragma unroll
    for (int ks = 0; ks < 4; ks++)
        ldsm4(qf[ks], lds_addr(sma + A_P + qoff + ks * 16));

    const int boff = rr * AP2 + grp * 8;            // K B-frags ([n][k] layout)
    const int voff = (grp * 8 + rr) * AP2;          // V trans B-frags ([k][n] layout)

    float m_i[2] = {-1e30f, -1e30f}, l_i[2] = {0.f, 0.f};
    float o[8][4] = {};

    for (int kt = 0; kt < ktmax; kt++) {
        const int k0 = kt * 64;
        if (kt + 1 < ktmax) CP_WAIT1(); else CP_WAIT0();
        __syncthreads();
        if (kt + 2 < ktmax) issue(kt + 2);

        __half* kbuf = sma + A_S0 + (kt % 3) * 2 * ASTG;
        __half* vbuf = kbuf + ASTG;

        // ---- S = Q K^T (exp2-domain: Q pre-scaled by 0.125*log2e) ----
        float sc[8][4] = {};
#pragma unroll
        for (int nf = 0; nf < 8; nf++) {
            uint32_t k8[8];
            ldsm4(k8,     lds_addr(kbuf + boff + nf * 8 * AP2));
            ldsm4(k8 + 4, lds_addr(kbuf + boff + nf * 8 * AP2 + 32));
#pragma unroll
            for (int ks = 0; ks < 4; ks++)
                mma_f16(sc[nf], qf[ks], k8[ks * 2], k8[ks * 2 + 1]);
        }

        // ---- causal mask ----
        if (kt >= 2 * qb) {
#pragma unroll
            for (int nf = 0; nf < 8; nf++)
#pragma unroll
                for (int j = 0; j < 4; j++) {
                    int col = k0 + nf * 8 + t4 * 2 + (j & 1);
                    int row = q0 + wrow + g + (j >> 1) * 8;
                    if (col > row) sc[nf][j] = -1e30f;
                }
        }

        // ---- online softmax (log2 domain) ----
#pragma unroll
        for (int hi = 0; hi < 2; hi++) {
            const int j0 = hi * 2;
            float mrow = -1e30f;
#pragma unroll
            for (int nf = 0; nf < 8; nf++)
                mrow = fmaxf(mrow, fmaxf(sc[nf][j0], sc[nf][j0 + 1]));
            mrow = fmaxf(mrow, __shfl_xor_sync(0xffffffffu, mrow, 1));
            mrow = fmaxf(mrow, __shfl_xor_sync(0xffffffffu, mrow, 2));
            float mnew = fmaxf(m_i[hi], mrow);
            float corr = ex2f(m_i[hi] - mnew);
            m_i[hi] = mnew;
            float ps = 0.f;
#pragma unroll
            for (int nf = 0; nf < 8; nf++) {
                float e0 = ex2f(sc[nf][j0] - mnew);
                float e1 = ex2f(sc[nf][j0 + 1] - mnew);
                sc[nf][j0] = e0; sc[nf][j0 + 1] = e1;
                ps += e0 + e1;
            }
            ps += __shfl_xor_sync(0xffffffffu, ps, 1);
            ps += __shfl_xor_sync(0xffffffffu, ps, 2);
            l_i[hi] = l_i[hi] * corr + ps;
#pragma unroll
            for (int nf = 0; nf < 8; nf++) {
                o[nf][j0] *= corr;
                o[nf][j0 + 1] *= corr;
            }
        }

        // ---- P -> smem (warp-private rows) ----
#pragma unroll
        for (int nf = 0; nf < 8; nf++) {
            int col = nf * 8 + t4 * 2;
            *(__half2*)(sma + A_P + (wrow + g) * AP2 + col) =
                __half2(__float2half(sc[nf][0]), __float2half(sc[nf][1]));
            *(__half2*)(sma + A_P + (wrow + g + 8) * AP2 + col) =
                __half2(__float2half(sc[nf][2]), __float2half(sc[nf][3]));
        }
        __syncwarp();

        // ---- O += P V  (V via ldmatrix.trans from [s][d]) ----
        uint32_t pf[4][4];
#pragma unroll
        for (int ks = 0; ks < 4; ks++)
            ldsm4(pf[ks], lds_addr(sma + A_P + qoff + ks * 16));
#pragma unroll
        for (int nf = 0; nf < 8; nf++) {
            uint32_t v8[8];
            ldsm4t(v8,     lds_addr(vbuf + voff + nf * 8));
            ldsm4t(v8 + 4, lds_addr(vbuf + voff + 32 * AP2 + nf * 8));
#pragma unroll
            for (int ks = 0; ks < 4; ks++)
                mma_f16(o[nf], pf[ks], v8[ks * 2], v8[ks * 2 + 1]);
        }
    }

    // ---- epilogue: O/l -> fp16, proj layout [b*S+s][h*64+d] ----
    const int b = bh >> 4, h = bh & 15;
    float inv_lo = 1.0f / l_i[0];
    float inv_hi = 1.0f / l_i[1];
#pragma unroll
    for (int nf = 0; nf < 8; nf++) {
        int srow = q0 + wrow + g;
        int col = h * 64 + nf * 8 + t4 * 2;
        size_t r0i = ((size_t)b * Ss + srow) * Ee + col;
        size_t r1i = ((size_t)b * Ss + srow + 8) * Ee + col;
        *(__half2*)&g_Oh[r0i] =
            __half2(__float2half(o[nf][0] * inv_lo), __float2half(o[nf][1] * inv_lo));
        *(__half2*)&g_Oh[r1i] =
            __half2(__float2half(o[nf][2] * inv_hi), __float2half(o[nf][3] * inv_hi));
    }
}

// ---------------------------------------------------------------------------
extern "C" void kernel_launch(void* const* d_in, const int* in_sizes, int n_in,
                              void* d_out, int out_size)
{
    const float* x  = (const float*)d_in[0];
    const float* Wq = (const float*)d_in[1];
    const float* Wk = (const float*)d_in[2];
    const float* Wv = (const float*)d_in[3];
    const float* Wo = (const float*)d_in[4];
    const float* bo = (const float*)d_in[5];
    float* out = (float*)d_out;

    cudaFuncSetAttribute(gemm_qkv,  cudaFuncAttributeMaxDynamicSharedMemorySize, GEMM_SMEM);
    cudaFuncSetAttribute(gemm_proj, cudaFuncAttributeMaxDynamicSharedMemorySize, GEMM_SMEM);
    cudaFuncSetAttribute(attn_f16,  cudaFuncAttributeMaxDynamicSharedMemorySize, ATTN_SMEM);

    prepass<<<dim3(32, 32, 20), dim3(32, 8)>>>(x, Wq, Wk, Wv, Wo);
    gemm_qkv<<<dim3(8, 32, 3), 256, GEMM_SMEM>>>();
    attn_f16<<<dim3(16, 32), 256, ATTN_SMEM>>>();
    gemm_proj<<<dim3(8, 32), 256, GEMM_SMEM>>>(bo, out);
}